// round 1
// baseline (speedup 1.0000x reference)
#include <cuda_runtime.h>
#include <math.h>
#include <float.h>

#define NN 3072
#define FIN 512
#define NHID 64
#define NHEADS 4
#define NGRAPH 3
#define GH (NGRAPH*NHEADS)
#define NCLASS 16
#define ALPHA 0.2f
#define NEGINF (-9000000000000000.0f)

// Scratch (device globals; no allocation allowed)
__device__ float g_Wh[GH * NN * NHID];          // [gh][n][o]
__device__ float g_f1[GH * NN];
__device__ float g_f2[GH * NN];
__device__ float g_hcat[NGRAPH * NN * (NHEADS*NHID)];  // [g][n][h*64+o]
__device__ float g_xib[NN * (NGRAPH*NCLASS)];          // [n][g*16+c]

// ---------------------------------------------------------------------------
// K1: Wh[gh][n][o] = sum_f x[n][f] * W[gh][f][o]
// 64x64 tile, BK=32, 256 threads, 4x4 micro-tile
// ---------------------------------------------------------------------------
__global__ void k_wh(const float* __restrict__ x, const float* __restrict__ W)
{
    __shared__ float As[32][65];   // As[k][row]
    __shared__ float Bs[32][68];   // Bs[k][col]
    const int gh = blockIdx.y;
    const int nbase = blockIdx.x * 64;
    const float* Wg = W + (size_t)gh * FIN * NHID;
    const int tid = threadIdx.x;
    const int tx = tid & 15, ty = tid >> 4;
    float acc[4][4] = {};

    for (int k0 = 0; k0 < FIN; k0 += 32) {
        {
            int r  = tid >> 3;            // 0..31
            int c4 = (tid & 7) * 4;       // 0..28
            float4 v0 = *(const float4*)(x + (size_t)(nbase + r)      * FIN + k0 + c4);
            float4 v1 = *(const float4*)(x + (size_t)(nbase + r + 32) * FIN + k0 + c4);
            As[c4+0][r]    = v0.x; As[c4+1][r]    = v0.y; As[c4+2][r]    = v0.z; As[c4+3][r]    = v0.w;
            As[c4+0][r+32] = v1.x; As[c4+1][r+32] = v1.y; As[c4+2][r+32] = v1.z; As[c4+3][r+32] = v1.w;
        }
        {
            int rb = tid >> 4;            // 0..15
            int cb = (tid & 15) * 4;      // 0..60
            *(float4*)&Bs[rb][cb]    = *(const float4*)(Wg + (size_t)(k0 + rb)      * NHID + cb);
            *(float4*)&Bs[rb+16][cb] = *(const float4*)(Wg + (size_t)(k0 + rb + 16) * NHID + cb);
        }
        __syncthreads();
        #pragma unroll
        for (int k = 0; k < 32; k++) {
            float a0 = As[k][ty*4+0], a1 = As[k][ty*4+1], a2 = As[k][ty*4+2], a3 = As[k][ty*4+3];
            float b0 = Bs[k][tx*4+0], b1 = Bs[k][tx*4+1], b2 = Bs[k][tx*4+2], b3 = Bs[k][tx*4+3];
            acc[0][0] += a0*b0; acc[0][1] += a0*b1; acc[0][2] += a0*b2; acc[0][3] += a0*b3;
            acc[1][0] += a1*b0; acc[1][1] += a1*b1; acc[1][2] += a1*b2; acc[1][3] += a1*b3;
            acc[2][0] += a2*b0; acc[2][1] += a2*b1; acc[2][2] += a2*b2; acc[2][3] += a2*b3;
            acc[3][0] += a3*b0; acc[3][1] += a3*b1; acc[3][2] += a3*b2; acc[3][3] += a3*b3;
        }
        __syncthreads();
    }
    float* out = g_Wh + ((size_t)gh * NN + nbase) * NHID;
    #pragma unroll
    for (int i = 0; i < 4; i++) {
        float4 v; v.x = acc[i][0]; v.y = acc[i][1]; v.z = acc[i][2]; v.w = acc[i][3];
        *(float4*)(out + (size_t)(ty*4 + i) * NHID + tx*4) = v;
    }
}

// ---------------------------------------------------------------------------
// K2: f1[gh][n] = Wh[gh][n][:] . a1[gh][:],  f2 with a2. Warp per row.
// ---------------------------------------------------------------------------
__global__ void k_f12(const float* __restrict__ a)
{
    int tid = threadIdx.x, w = tid >> 5, lane = tid & 31;
    long idx = (long)blockIdx.x * 8 + w;     // 0 .. GH*NN-1
    int gh = (int)(idx / NN);
    int n  = (int)(idx % NN);
    const float* whr = g_Wh + ((size_t)gh * NN + n) * NHID;
    const float* ag  = a + (size_t)gh * 2 * NHID;
    float w0 = whr[lane], w1 = whr[lane + 32];
    float s1 = w0 * ag[lane]      + w1 * ag[lane + 32];
    float s2 = w0 * ag[64 + lane] + w1 * ag[64 + lane + 32];
    #pragma unroll
    for (int o = 16; o >= 1; o >>= 1) {
        s1 += __shfl_xor_sync(0xffffffffu, s1, o);
        s2 += __shfl_xor_sync(0xffffffffu, s2, o);
    }
    if (lane == 0) {
        g_f1[(size_t)gh * NN + n] = s1;
        g_f2[(size_t)gh * NN + n] = s2;
    }
}

// ---------------------------------------------------------------------------
// K3: attention + elu.  Block = 256 threads = 8 warps, warp handles 4 rows.
// Online softmax over m in chunks of 64. g slowest in block order (adj L2 reuse).
// ---------------------------------------------------------------------------
__global__ void k_att(const int* __restrict__ adj)
{
    __shared__ float WhS[64][64];
    __shared__ float f2s[64];
    __shared__ float pS[8][4][64];

    const int tid = threadIdx.x, w = tid >> 5, lane = tid & 31;
    const int bid = blockIdx.x;
    const int tile = bid % 96;
    const int h    = (bid / 96) % NHEADS;
    const int g    = bid / (96 * NHEADS);
    const int gh   = g * NHEADS + h;
    const int nbase = tile * 32;

    int   nrow[4];
    float f1v[4], M[4], S[4], acc0[4], acc1[4];
    #pragma unroll
    for (int r = 0; r < 4; r++) {
        nrow[r] = nbase + w * 4 + r;
        f1v[r]  = g_f1[(size_t)gh * NN + nrow[r]];
        M[r] = -FLT_MAX; S[r] = 0.f; acc0[r] = 0.f; acc1[r] = 0.f;
    }

    const float* Whg  = g_Wh + (size_t)gh * NN * NHID;
    const int*   adjg = adj  + (size_t)g * NN * NN;
    const float* f2g  = g_f2 + (size_t)gh * NN;

    for (int m0 = 0; m0 < NN; m0 += 64) {
        {   // stage Wh chunk [64][64]
            int r  = tid >> 2;
            int cb = (tid & 3) * 16;
            const float* src = Whg + (size_t)(m0 + r) * NHID + cb;
            #pragma unroll
            for (int j = 0; j < 4; j++)
                *(float4*)&WhS[r][cb + 4*j] = *(const float4*)(src + 4*j);
        }
        if (tid < 64) f2s[tid] = f2g[m0 + tid];
        __syncthreads();

        #pragma unroll
        for (int r = 0; r < 4; r++) {
            const int* ap = adjg + (size_t)nrow[r] * NN + m0;
            int ai0 = ap[lane], ai1 = ap[lane + 32];
            float e0 = f1v[r] + f2s[lane];
            float e1 = f1v[r] + f2s[lane + 32];
            e0 = (e0 > 0.f) ? e0 : ALPHA * e0;
            e1 = (e1 > 0.f) ? e1 : ALPHA * e1;
            e0 = (ai0 > 0) ? e0 : NEGINF;
            e1 = (ai1 > 0) ? e1 : NEGINF;
            float cm = fmaxf(e0, e1);
            #pragma unroll
            for (int o = 16; o >= 1; o >>= 1)
                cm = fmaxf(cm, __shfl_xor_sync(0xffffffffu, cm, o));
            float Mn = fmaxf(M[r], cm);
            float sc = __expf(M[r] - Mn);
            float p0 = __expf(e0 - Mn);
            float p1 = __expf(e1 - Mn);
            float ps = p0 + p1;
            #pragma unroll
            for (int o = 16; o >= 1; o >>= 1)
                ps += __shfl_xor_sync(0xffffffffu, ps, o);
            S[r] = S[r] * sc + ps;
            acc0[r] *= sc; acc1[r] *= sc;
            M[r] = Mn;
            pS[w][r][lane]      = p0;
            pS[w][r][lane + 32] = p1;
        }
        __syncwarp();

        #pragma unroll 4
        for (int m = 0; m < 64; m++) {
            float w0 = WhS[m][lane];
            float w1 = WhS[m][lane + 32];
            #pragma unroll
            for (int r = 0; r < 4; r++) {
                float pv = pS[w][r][m];
                acc0[r] += pv * w0;
                acc1[r] += pv * w1;
            }
        }
        __syncthreads();
    }

    #pragma unroll
    for (int r = 0; r < 4; r++) {
        float inv = 1.0f / S[r];
        float o0 = acc0[r] * inv;
        float o1 = acc1[r] * inv;
        o0 = (o0 > 0.f) ? o0 : expm1f(o0);   // elu
        o1 = (o1 > 0.f) ? o1 : expm1f(o1);
        float* dst = g_hcat + ((size_t)g * NN + nrow[r]) * (NHEADS*NHID) + h * NHID;
        dst[lane]      = o0;
        dst[lane + 32] = o1;
    }
}

// ---------------------------------------------------------------------------
// K4: xi[g][n][c] = elu(hcat[g][n][:] . W_int[c][:] + b_int[c]) -> g_xib[n][g*16+c]
// ---------------------------------------------------------------------------
__global__ void k_xi(const float* __restrict__ W_int, const float* __restrict__ b_int)
{
    __shared__ float Ws[NCLASS * 256];
    __shared__ float bs[NCLASS];
    const int tid = threadIdx.x, w = tid >> 5, lane = tid & 31;
    #pragma unroll
    for (int j = 0; j < 4; j++)
        *(float4*)&Ws[tid * 4 + j * 1024] = *(const float4*)(W_int + tid * 4 + j * 1024);
    if (tid < NCLASS) bs[tid] = b_int[tid];
    __syncthreads();

    long idx = (long)blockIdx.x * 8 + w;   // 0 .. NGRAPH*NN-1
    int g = (int)(idx / NN);
    int n = (int)(idx % NN);
    const float* hrow = g_hcat + ((size_t)g * NN + n) * 256;
    float v[8];
    #pragma unroll
    for (int j = 0; j < 8; j++) v[j] = hrow[lane + 32 * j];

    for (int c = 0; c < NCLASS; c++) {
        const float* wc = Ws + c * 256;
        float s = 0.f;
        #pragma unroll
        for (int j = 0; j < 8; j++) s += v[j] * wc[lane + 32 * j];
        #pragma unroll
        for (int o = 16; o >= 1; o >>= 1) s += __shfl_xor_sync(0xffffffffu, s, o);
        if (lane == 0) {
            float t = s + bs[c];
            t = (t > 0.f) ? t : expm1f(t);
            g_xib[(size_t)n * (NGRAPH*NCLASS) + g * NCLASS + c] = t;
        }
    }
}

// ---------------------------------------------------------------------------
// K5: out[n][c] = log_softmax( xib[n][:] @ W_fus^T + b_fus )
// ---------------------------------------------------------------------------
__global__ void k_out(const float* __restrict__ W_fus, const float* __restrict__ b_fus,
                      float* __restrict__ out)
{
    __shared__ float Wf[NCLASS * 48];
    __shared__ float bf[NCLASS];
    const int tid = threadIdx.x;
    for (int i = tid; i < NCLASS * 48; i += 256) Wf[i] = W_fus[i];
    if (tid < NCLASS) bf[tid] = b_fus[tid];
    __syncthreads();

    int n = blockIdx.x * 256 + tid;
    const float* xr = g_xib + (size_t)n * 48;
    float xv[48];
    #pragma unroll
    for (int j = 0; j < 48; j++) xv[j] = xr[j];

    float o[NCLASS];
    float mx = -FLT_MAX;
    #pragma unroll
    for (int c = 0; c < NCLASS; c++) {
        float s = bf[c];
        #pragma unroll
        for (int j = 0; j < 48; j++) s += xv[j] * Wf[c * 48 + j];
        o[c] = s;
        mx = fmaxf(mx, s);
    }
    float sum = 0.f;
    #pragma unroll
    for (int c = 0; c < NCLASS; c++) sum += expf(o[c] - mx);
    float lse = mx + logf(sum);
    float* dst = out + (size_t)n * NCLASS;
    #pragma unroll
    for (int c = 0; c < NCLASS; c++) dst[c] = o[c] - lse;
}

// ---------------------------------------------------------------------------
// K6: l1 = mean |W_fus|, written to trailing output element(s)
// ---------------------------------------------------------------------------
__global__ void k_l1(const float* __restrict__ W_fus, float* __restrict__ out, int out_size)
{
    __shared__ float red[256];
    int tid = threadIdx.x;
    float s = 0.f;
    for (int i = tid; i < NCLASS * 48; i += 256) s += fabsf(W_fus[i]);
    red[tid] = s;
    __syncthreads();
    for (int o = 128; o >= 1; o >>= 1) {
        if (tid < o) red[tid] += red[tid + o];
        __syncthreads();
    }
    if (tid == 0) {
        float l1 = red[0] / (float)(NCLASS * 48);
        for (int i = NN * NCLASS; i < out_size; i++) out[i] = l1;
    }
}

extern "C" void kernel_launch(void* const* d_in, const int* in_sizes, int n_in,
                              void* d_out, int out_size)
{
    const float* x     = (const float*)d_in[0];
    const int*   adj   = (const int*)  d_in[1];
    const float* W     = (const float*)d_in[2];
    const float* a     = (const float*)d_in[3];
    const float* W_int = (const float*)d_in[4];
    const float* b_int = (const float*)d_in[5];
    const float* W_fus = (const float*)d_in[6];
    const float* b_fus = (const float*)d_in[7];
    float* out = (float*)d_out;

    k_wh <<<dim3(NN/64, GH), 256>>>(x, W);
    k_f12<<<GH * NN / 8, 256>>>(a);
    k_att<<<NGRAPH * NHEADS * (NN/32), 256>>>(adj);
    k_xi <<<NGRAPH * NN / 8, 256>>>(W_int, b_int);
    k_out<<<NN/256, 256>>>(W_fus, b_fus, out);
    k_l1 <<<1, 256>>>(W_fus, out, out_size);
}

// round 2
// speedup vs baseline: 1.6254x; 1.6254x over previous
#include <cuda_runtime.h>
#include <math.h>
#include <float.h>

#define NN 3072
#define FIN 512
#define NHID 64
#define NHEADS 4
#define NGRAPH 3
#define GH (NGRAPH*NHEADS)
#define NCLASS 16
#define ALPHA 0.2f
#define NEGINF (-9000000000000000.0f)

typedef unsigned long long u64;

// packed fp32x2 helpers (sm_103a FFMA2)
__device__ __forceinline__ u64 ffma2(u64 a, u64 b, u64 c) {
    u64 d;
    asm("fma.rn.f32x2 %0, %1, %2, %3;" : "=l"(d) : "l"(a), "l"(b), "l"(c));
    return d;
}
__device__ __forceinline__ u64 bcast2(float x) {
    u64 d; asm("mov.b64 %0, {%1, %1};" : "=l"(d) : "f"(x)); return d;
}
__device__ __forceinline__ float2 unpack2(u64 v) {
    float2 r; asm("mov.b64 {%0, %1}, %2;" : "=f"(r.x), "=f"(r.y) : "l"(v)); return r;
}

// Scratch (device globals; no allocation allowed)
__device__ float g_Wh[GH * NN * NHID];          // [gh][n][o]
__device__ float g_f1[GH * NN];
__device__ float g_f2[GH * NN];
__device__ float g_hcat[NGRAPH * NN * (NHEADS*NHID)];  // [g][n][h*64+o]
__device__ float g_xib[NN * (NGRAPH*NCLASS)];          // [n][g*16+c]

// ---------------------------------------------------------------------------
// K1: Wh[gh][n][o] = sum_f x[n][f] * W[gh][f][o]
// 64x64 tile, BK=32, 256 threads, 4x4 micro-tile via FFMA2
// ---------------------------------------------------------------------------
__global__ void k_wh(const float* __restrict__ x, const float* __restrict__ W)
{
    __shared__ float As[32][65];   // As[k][row]
    __shared__ float Bs[32][68];   // Bs[k][col]
    const int gh = blockIdx.y;
    const int nbase = blockIdx.x * 64;
    const float* Wg = W + (size_t)gh * FIN * NHID;
    const int tid = threadIdx.x;
    const int tx = tid & 15, ty = tid >> 4;
    u64 acc[4][2];
    #pragma unroll
    for (int i = 0; i < 4; i++) { acc[i][0] = bcast2(0.f); acc[i][1] = bcast2(0.f); }

    for (int k0 = 0; k0 < FIN; k0 += 32) {
        {
            int r  = tid >> 3;            // 0..31
            int c4 = (tid & 7) * 4;       // 0..28
            float4 v0 = *(const float4*)(x + (size_t)(nbase + r)      * FIN + k0 + c4);
            float4 v1 = *(const float4*)(x + (size_t)(nbase + r + 32) * FIN + k0 + c4);
            As[c4+0][r]    = v0.x; As[c4+1][r]    = v0.y; As[c4+2][r]    = v0.z; As[c4+3][r]    = v0.w;
            As[c4+0][r+32] = v1.x; As[c4+1][r+32] = v1.y; As[c4+2][r+32] = v1.z; As[c4+3][r+32] = v1.w;
        }
        {
            int rb = tid >> 4;            // 0..15
            int cb = (tid & 15) * 4;      // 0..60
            *(float4*)&Bs[rb][cb]    = *(const float4*)(Wg + (size_t)(k0 + rb)      * NHID + cb);
            *(float4*)&Bs[rb+16][cb] = *(const float4*)(Wg + (size_t)(k0 + rb + 16) * NHID + cb);
        }
        __syncthreads();
        #pragma unroll
        for (int k = 0; k < 32; k++) {
            u64 b01 = *(const u64*)&Bs[k][tx*4];
            u64 b23 = *(const u64*)&Bs[k][tx*4 + 2];
            #pragma unroll
            for (int i = 0; i < 4; i++) {
                u64 pa = bcast2(As[k][ty*4 + i]);
                acc[i][0] = ffma2(pa, b01, acc[i][0]);
                acc[i][1] = ffma2(pa, b23, acc[i][1]);
            }
        }
        __syncthreads();
    }
    float* out = g_Wh + ((size_t)gh * NN + nbase) * NHID;
    #pragma unroll
    for (int i = 0; i < 4; i++) {
        float2 lo = unpack2(acc[i][0]);
        float2 hi = unpack2(acc[i][1]);
        float4 v; v.x = lo.x; v.y = lo.y; v.z = hi.x; v.w = hi.y;
        *(float4*)(out + (size_t)(ty*4 + i) * NHID + tx*4) = v;
    }
}

// ---------------------------------------------------------------------------
// K2: f1/f2 dot products. Warp per row.
// ---------------------------------------------------------------------------
__global__ void k_f12(const float* __restrict__ a)
{
    int tid = threadIdx.x, w = tid >> 5, lane = tid & 31;
    long idx = (long)blockIdx.x * 8 + w;     // 0 .. GH*NN-1
    int gh = (int)(idx / NN);
    int n  = (int)(idx % NN);
    const float* whr = g_Wh + ((size_t)gh * NN + n) * NHID;
    const float* ag  = a + (size_t)gh * 2 * NHID;
    float w0 = whr[lane], w1 = whr[lane + 32];
    float s1 = w0 * ag[lane]      + w1 * ag[lane + 32];
    float s2 = w0 * ag[64 + lane] + w1 * ag[64 + lane + 32];
    #pragma unroll
    for (int o = 16; o >= 1; o >>= 1) {
        s1 += __shfl_xor_sync(0xffffffffu, s1, o);
        s2 += __shfl_xor_sync(0xffffffffu, s2, o);
    }
    if (lane == 0) {
        g_f1[(size_t)gh * NN + n] = s1;
        g_f2[(size_t)gh * NN + n] = s2;
    }
}

// ---------------------------------------------------------------------------
// K3: attention + elu.
// No online max (exp range bounded: exact softmax with shift 0).
// 8 warps x 16 rows = 128 rows/block. FFMA2 mainloop.
// ---------------------------------------------------------------------------
#define RPW 16
__global__ void __launch_bounds__(256, 2) k_att(const int* __restrict__ adj)
{
    __shared__ float WhS[64][64];          // 16 KB
    __shared__ float pS[8][RPW][64];       // 32 KB

    const int tid = threadIdx.x, w = tid >> 5, lane = tid & 31;
    const int bid = blockIdx.x;
    const int tile = bid % 24;
    const int h    = (bid / 24) % NHEADS;
    const int g    = bid / (24 * NHEADS);
    const int gh   = g * NHEADS + h;
    const int nbase = tile * 128 + w * RPW;

    float f1v[RPW], Sacc[RPW];
    u64 acc[RPW];
    #pragma unroll
    for (int r = 0; r < RPW; r++) {
        f1v[r] = g_f1[(size_t)gh * NN + nbase + r];
        Sacc[r] = 0.f;
        acc[r] = bcast2(0.f);
    }

    const float* Whg  = g_Wh + (size_t)gh * NN * NHID;
    const int*   adjg = adj  + (size_t)g * NN * NN;
    const float* f2g  = g_f2 + (size_t)gh * NN;

    for (int m0 = 0; m0 < NN; m0 += 64) {
        {   // stage Wh chunk [64][64]
            int r  = tid >> 2;
            int cb = (tid & 3) * 16;
            const float* src = Whg + (size_t)(m0 + r) * NHID + cb;
            #pragma unroll
            for (int j = 0; j < 4; j++)
                *(float4*)&WhS[r][cb + 4*j] = *(const float4*)(src + 4*j);
        }
        __syncthreads();

        // p-phase: lane handles m = m0 + 2*lane, 2*lane+1 for each of its rows
        float2 f2p = ((const float2*)(f2g + m0))[lane];
        #pragma unroll
        for (int r = 0; r < RPW; r++) {
            int2 av = ((const int2*)(adjg + (size_t)(nbase + r) * NN + m0))[lane];
            float e0 = f1v[r] + f2p.x;
            float e1 = f1v[r] + f2p.y;
            e0 = (e0 > 0.f) ? e0 : ALPHA * e0;
            e1 = (e1 > 0.f) ? e1 : ALPHA * e1;
            e0 = (av.x > 0) ? e0 : NEGINF;
            e1 = (av.y > 0) ? e1 : NEGINF;
            float p0 = __expf(e0);
            float p1 = __expf(e1);
            Sacc[r] += p0 + p1;
            float2 pp; pp.x = p0; pp.y = p1;
            ((float2*)pS[w][r])[lane] = pp;
        }
        __syncwarp();

        // mainloop: FFMA2, 4 m's per step
        #pragma unroll 4
        for (int mq = 0; mq < 64; mq += 4) {
            u64 wv0 = *(const u64*)&WhS[mq + 0][2*lane];
            u64 wv1 = *(const u64*)&WhS[mq + 1][2*lane];
            u64 wv2 = *(const u64*)&WhS[mq + 2][2*lane];
            u64 wv3 = *(const u64*)&WhS[mq + 3][2*lane];
            #pragma unroll
            for (int r = 0; r < RPW; r++) {
                float4 pv = *(const float4*)&pS[w][r][mq];
                acc[r] = ffma2(bcast2(pv.x), wv0, acc[r]);
                acc[r] = ffma2(bcast2(pv.y), wv1, acc[r]);
                acc[r] = ffma2(bcast2(pv.z), wv2, acc[r]);
                acc[r] = ffma2(bcast2(pv.w), wv3, acc[r]);
            }
        }
        __syncthreads();
    }

    #pragma unroll
    for (int r = 0; r < RPW; r++) {
        float S = Sacc[r];
        #pragma unroll
        for (int o = 16; o >= 1; o >>= 1)
            S += __shfl_xor_sync(0xffffffffu, S, o);
        float inv = 1.0f / S;
        float2 av = unpack2(acc[r]);
        float o0 = av.x * inv, o1 = av.y * inv;
        o0 = (o0 > 0.f) ? o0 : expm1f(o0);
        o1 = (o1 > 0.f) ? o1 : expm1f(o1);
        float2 ov; ov.x = o0; ov.y = o1;
        float* dst = g_hcat + ((size_t)g * NN + nbase + r) * (NHEADS*NHID) + h * NHID;
        *(float2*)(dst + 2*lane) = ov;
    }
}

// ---------------------------------------------------------------------------
// K4: xi[g][n][c] = elu(hcat . W_int[c] + b_int[c]) -> g_xib[n][g*16+c]
// ---------------------------------------------------------------------------
__global__ void k_xi(const float* __restrict__ W_int, const float* __restrict__ b_int)
{
    __shared__ float Ws[NCLASS * 256];
    __shared__ float bs[NCLASS];
    const int tid = threadIdx.x, w = tid >> 5, lane = tid & 31;
    #pragma unroll
    for (int j = 0; j < 4; j++)
        *(float4*)&Ws[tid * 4 + j * 1024] = *(const float4*)(W_int + tid * 4 + j * 1024);
    if (tid < NCLASS) bs[tid] = b_int[tid];
    __syncthreads();

    long idx = (long)blockIdx.x * 8 + w;   // 0 .. NGRAPH*NN-1
    int g = (int)(idx / NN);
    int n = (int)(idx % NN);
    const float* hrow = g_hcat + ((size_t)g * NN + n) * 256;
    float v[8];
    #pragma unroll
    for (int j = 0; j < 8; j++) v[j] = hrow[lane + 32 * j];

    for (int c = 0; c < NCLASS; c++) {
        const float* wc = Ws + c * 256;
        float s = 0.f;
        #pragma unroll
        for (int j = 0; j < 8; j++) s += v[j] * wc[lane + 32 * j];
        #pragma unroll
        for (int o = 16; o >= 1; o >>= 1) s += __shfl_xor_sync(0xffffffffu, s, o);
        if (lane == 0) {
            float t = s + bs[c];
            t = (t > 0.f) ? t : expm1f(t);
            g_xib[(size_t)n * (NGRAPH*NCLASS) + g * NCLASS + c] = t;
        }
    }
}

// ---------------------------------------------------------------------------
// K5: out[n][c] = log_softmax( xib[n][:] @ W_fus^T + b_fus )
// ---------------------------------------------------------------------------
__global__ void k_out(const float* __restrict__ W_fus, const float* __restrict__ b_fus,
                      float* __restrict__ out)
{
    __shared__ float Wf[NCLASS * 48];
    __shared__ float bf[NCLASS];
    const int tid = threadIdx.x;
    for (int i = tid; i < NCLASS * 48; i += 256) Wf[i] = W_fus[i];
    if (tid < NCLASS) bf[tid] = b_fus[tid];
    __syncthreads();

    int n = blockIdx.x * 256 + tid;
    const float* xr = g_xib + (size_t)n * 48;
    float xv[48];
    #pragma unroll
    for (int j = 0; j < 48; j++) xv[j] = xr[j];

    float o[NCLASS];
    float mx = -FLT_MAX;
    #pragma unroll
    for (int c = 0; c < NCLASS; c++) {
        float s = bf[c];
        #pragma unroll
        for (int j = 0; j < 48; j++) s += xv[j] * Wf[c * 48 + j];
        o[c] = s;
        mx = fmaxf(mx, s);
    }
    float sum = 0.f;
    #pragma unroll
    for (int c = 0; c < NCLASS; c++) sum += expf(o[c] - mx);
    float lse = mx + logf(sum);
    float* dst = out + (size_t)n * NCLASS;
    #pragma unroll
    for (int c = 0; c < NCLASS; c++) dst[c] = o[c] - lse;
}

// ---------------------------------------------------------------------------
// K6: l1 = mean |W_fus|
// ---------------------------------------------------------------------------
__global__ void k_l1(const float* __restrict__ W_fus, float* __restrict__ out, int out_size)
{
    __shared__ float red[256];
    int tid = threadIdx.x;
    float s = 0.f;
    for (int i = tid; i < NCLASS * 48; i += 256) s += fabsf(W_fus[i]);
    red[tid] = s;
    __syncthreads();
    for (int o = 128; o >= 1; o >>= 1) {
        if (tid < o) red[tid] += red[tid + o];
        __syncthreads();
    }
    if (tid == 0) {
        float l1 = red[0] / (float)(NCLASS * 48);
        for (int i = NN * NCLASS; i < out_size; i++) out[i] = l1;
    }
}

extern "C" void kernel_launch(void* const* d_in, const int* in_sizes, int n_in,
                              void* d_out, int out_size)
{
    const float* x     = (const float*)d_in[0];
    const int*   adj   = (const int*)  d_in[1];
    const float* W     = (const float*)d_in[2];
    const float* a     = (const float*)d_in[3];
    const float* W_int = (const float*)d_in[4];
    const float* b_int = (const float*)d_in[5];
    const float* W_fus = (const float*)d_in[6];
    const float* b_fus = (const float*)d_in[7];
    float* out = (float*)d_out;

    k_wh <<<dim3(NN/64, GH), 256>>>(x, W);
    k_f12<<<GH * NN / 8, 256>>>(a);
    k_att<<<NGRAPH * NHEADS * (NN/128), 256>>>(adj);
    k_xi <<<NGRAPH * NN / 8, 256>>>(W_int, b_int);
    k_out<<<NN/256, 256>>>(W_fus, b_fus, out);
    k_l1 <<<1, 256>>>(W_fus, out, out_size);
}

// round 6
// speedup vs baseline: 2.9894x; 1.8392x over previous
#include <cuda_runtime.h>
#include <math.h>
#include <float.h>

#define NN 3072
#define FIN 512
#define NHID 64
#define NHEADS 4
#define NGRAPH 3
#define GH (NGRAPH*NHEADS)
#define NCLASS 16
#define ALPHA 0.2f

typedef unsigned long long u64;
typedef unsigned int u32;

// ---------------- packed fp32x2 helpers (FFMA2) ----------------
__device__ __forceinline__ u64 ffma2(u64 a, u64 b, u64 c) {
    u64 d; asm("fma.rn.f32x2 %0, %1, %2, %3;" : "=l"(d) : "l"(a), "l"(b), "l"(c)); return d;
}
__device__ __forceinline__ u64 bcast2(float x) {
    u64 d; asm("mov.b64 %0, {%1, %1};" : "=l"(d) : "f"(x)); return d;
}
__device__ __forceinline__ float2 unpack2(u64 v) {
    float2 r; asm("mov.b64 {%0, %1}, %2;" : "=f"(r.x), "=f"(r.y) : "l"(v)); return r;
}
__device__ __forceinline__ u32 tf32r(float x) {
    u32 u; asm("cvt.rna.tf32.f32 %0, %1;" : "=r"(u) : "f"(x)); return u;
}
// warp mma m16n8k8 tf32 (portable PTX, maps to fallback HMMA on sm_103)
__device__ __forceinline__ void mma_tf32(float* c, u32 a0, u32 a1, u32 a2, u32 a3,
                                         u32 b0, u32 b1) {
    asm volatile(
        "mma.sync.aligned.m16n8k8.row.col.f32.tf32.tf32.f32 "
        "{%0,%1,%2,%3}, {%4,%5,%6,%7}, {%8,%9}, {%0,%1,%2,%3};"
        : "+f"(c[0]), "+f"(c[1]), "+f"(c[2]), "+f"(c[3])
        : "r"(a0), "r"(a1), "r"(a2), "r"(a3), "r"(b0), "r"(b1));
}

// ---------------- device scratch ----------------
__device__ float  g_Wh[GH * NN * NHID];          // [gh][n][o]
__device__ float4 g_pf1[GH * NN];                // (f1, exp(f1), exp(a*f1), 0)
__device__ float4 g_pf2[GH * NN];                // (f2, exp(f2), exp(a*f2), 0)
__device__ u32    g_abits[NGRAPH * NN * (NN/32)];// [g][n][m/32]
__device__ float  g_hcat[NGRAPH * NN * (NHEADS*NHID)];
__device__ float  g_xib[NN * (NGRAPH*NCLASS)];

// ---------------------------------------------------------------------------
// K1: Wh = x @ W  (FFMA2 64x64 tiles)
// ---------------------------------------------------------------------------
__global__ void k_wh(const float* __restrict__ x, const float* __restrict__ W)
{
    __shared__ float As[32][65];
    __shared__ float Bs[32][68];
    const int gh = blockIdx.y;
    const int nbase = blockIdx.x * 64;
    const float* Wg = W + (size_t)gh * FIN * NHID;
    const int tid = threadIdx.x;
    const int tx = tid & 15, ty = tid >> 4;
    u64 acc[4][2];
    #pragma unroll
    for (int i = 0; i < 4; i++) { acc[i][0] = bcast2(0.f); acc[i][1] = bcast2(0.f); }

    for (int k0 = 0; k0 < FIN; k0 += 32) {
        {
            int r  = tid >> 3;
            int c4 = (tid & 7) * 4;
            float4 v0 = *(const float4*)(x + (size_t)(nbase + r)      * FIN + k0 + c4);
            float4 v1 = *(const float4*)(x + (size_t)(nbase + r + 32) * FIN + k0 + c4);
            As[c4+0][r]    = v0.x; As[c4+1][r]    = v0.y; As[c4+2][r]    = v0.z; As[c4+3][r]    = v0.w;
            As[c4+0][r+32] = v1.x; As[c4+1][r+32] = v1.y; As[c4+2][r+32] = v1.z; As[c4+3][r+32] = v1.w;
        }
        {
            int rb = tid >> 4;
            int cb = (tid & 15) * 4;
            *(float4*)&Bs[rb][cb]    = *(const float4*)(Wg + (size_t)(k0 + rb)      * NHID + cb);
            *(float4*)&Bs[rb+16][cb] = *(const float4*)(Wg + (size_t)(k0 + rb + 16) * NHID + cb);
        }
        __syncthreads();
        #pragma unroll
        for (int k = 0; k < 32; k++) {
            u64 b01 = *(const u64*)&Bs[k][tx*4];
            u64 b23 = *(const u64*)&Bs[k][tx*4 + 2];
            #pragma unroll
            for (int i = 0; i < 4; i++) {
                u64 pa = bcast2(As[k][ty*4 + i]);
                acc[i][0] = ffma2(pa, b01, acc[i][0]);
                acc[i][1] = ffma2(pa, b23, acc[i][1]);
            }
        }
        __syncthreads();
    }
    float* out = g_Wh + ((size_t)gh * NN + nbase) * NHID;
    #pragma unroll
    for (int i = 0; i < 4; i++) {
        float2 lo = unpack2(acc[i][0]);
        float2 hi = unpack2(acc[i][1]);
        float4 v; v.x = lo.x; v.y = lo.y; v.z = hi.x; v.w = hi.y;
        *(float4*)(out + (size_t)(ty*4 + i) * NHID + tx*4) = v;
    }
}

// ---------------------------------------------------------------------------
// K1b: pack adjacency into bitmask
// ---------------------------------------------------------------------------
__global__ void k_pack(const int* __restrict__ adj)
{
    int w = threadIdx.x >> 5, lane = threadIdx.x & 31;
    long idx = (long)blockIdx.x * 8 + w;     // 0 .. NGRAPH*NN-1
    const int* ar = adj + (size_t)idx * NN;
    u32* dst = g_abits + (size_t)idx * (NN/32);
    for (int w0 = 0; w0 < NN/32; w0++) {
        int v = ar[w0 * 32 + lane];
        u32 b = __ballot_sync(0xffffffffu, v > 0);
        if (lane == 0) dst[w0] = b;
    }
}

// ---------------------------------------------------------------------------
// K2: f1/f2 dots + separated exponentials
// ---------------------------------------------------------------------------
__global__ void k_f12(const float* __restrict__ a)
{
    int tid = threadIdx.x, w = tid >> 5, lane = tid & 31;
    long idx = (long)blockIdx.x * 8 + w;
    int gh = (int)(idx / NN);
    int n  = (int)(idx % NN);
    const float* whr = g_Wh + ((size_t)gh * NN + n) * NHID;
    const float* ag  = a + (size_t)gh * 2 * NHID;
    float w0 = whr[lane], w1 = whr[lane + 32];
    float s1 = w0 * ag[lane]      + w1 * ag[lane + 32];
    float s2 = w0 * ag[64 + lane] + w1 * ag[64 + lane + 32];
    #pragma unroll
    for (int o = 16; o >= 1; o >>= 1) {
        s1 += __shfl_xor_sync(0xffffffffu, s1, o);
        s2 += __shfl_xor_sync(0xffffffffu, s2, o);
    }
    if (lane == 0) {
        float4 v1; v1.x = s1; v1.y = __expf(s1); v1.z = __expf(ALPHA * s1); v1.w = 0.f;
        float4 v2; v2.x = s2; v2.y = __expf(s2); v2.z = __expf(ALPHA * s2); v2.w = 0.f;
        g_pf1[(size_t)gh * NN + n] = v1;
        g_pf2[(size_t)gh * NN + n] = v2;
    }
}

// ---------------------------------------------------------------------------
// K3: attention via warp-mma tf32, exp-separated p, exact (shift-0) softmax.
// 256 thr = 8 warps, 128 rows/CTA (warp w: rows w*16..+15). 48 chunks of 64 m.
// ---------------------------------------------------------------------------
__device__ __forceinline__ float p_of(const float4 p1, const float4 f2v, u32 bit) {
    float t = p1.x + f2v.x;
    float v = (t > 0.f) ? (p1.y * f2v.y) : (p1.z * f2v.z);
    return bit ? v : 0.f;
}
__device__ __forceinline__ float eluf(float v) {
    return (v > 0.f) ? v : expm1f(v);
}

__global__ void __launch_bounds__(256, 2) k_att_mma()
{
    __shared__ float  WhS[64][72];     // [m][o], pad 72 -> B-frag LDS conflict-free
    __shared__ float4 f2S[64];         // (f2, E2, E2a, -)
    __shared__ float  sS[128];

    const int tid = threadIdx.x, w = tid >> 5, l = tid & 31;
    const int bid  = blockIdx.x;
    const int tile = bid % 24;
    const int h    = (bid / 24) % NHEADS;
    const int g    = bid / (24 * NHEADS);
    const int gh   = g * NHEADS + h;
    const int nbase = tile * 128;

    const int rlo = w * 16 + (l >> 2);   // local row (0..127)
    const int rhi = rlo + 8;

    const float4 p1lo = g_pf1[(size_t)gh * NN + nbase + rlo];
    const float4 p1hi = g_pf1[(size_t)gh * NN + nbase + rhi];
    const float4* pf2 = g_pf2 + (size_t)gh * NN;
    const u32* ab_lo  = g_abits + ((size_t)g * NN + nbase + rlo) * (NN/32);
    const u32* ab_hi  = g_abits + ((size_t)g * NN + nbase + rhi) * (NN/32);
    const float* Whg  = g_Wh + (size_t)gh * NN * NHID;

    float c[8][4];
    #pragma unroll
    for (int t = 0; t < 8; t++) { c[t][0]=0.f; c[t][1]=0.f; c[t][2]=0.f; c[t][3]=0.f; }
    float Slo = 0.f, Shi = 0.f;

    // prefetch chunk 0
    float4 wpre[4]; float4 fpre = make_float4(0,0,0,0);
    u32 abl0, abl1, abh0, abh1;
    {
        const float4* src = (const float4*)(Whg + (size_t)(tid >> 2) * NHID + (tid & 3) * 16);
        #pragma unroll
        for (int j = 0; j < 4; j++) wpre[j] = src[j];
        if (tid < 64) fpre = pf2[tid];
        abl0 = ab_lo[0]; abl1 = ab_lo[1];
        abh0 = ab_hi[0]; abh1 = ab_hi[1];
    }

    for (int i = 0; i < NN/64; i++) {
        __syncthreads();
        {   // store staged chunk (tf32-rounded B)
            int r = tid >> 2, cb = (tid & 3) * 16;
            #pragma unroll
            for (int j = 0; j < 4; j++) {
                float4 v = wpre[j];
                v.x = __uint_as_float(tf32r(v.x));
                v.y = __uint_as_float(tf32r(v.y));
                v.z = __uint_as_float(tf32r(v.z));
                v.w = __uint_as_float(tf32r(v.w));
                *(float4*)&WhS[r][cb + 4*j] = v;
            }
            if (tid < 64) f2S[tid] = fpre;
        }
        const u32 wl0 = abl0, wl1 = abl1, wh0 = abh0, wh1 = abh1;
        __syncthreads();

        if (i + 1 < NN/64) {   // prefetch next chunk into regs
            int m0n = (i + 1) * 64;
            const float4* src = (const float4*)(Whg + (size_t)(m0n + (tid >> 2)) * NHID + (tid & 3) * 16);
            #pragma unroll
            for (int j = 0; j < 4; j++) wpre[j] = src[j];
            if (tid < 64) fpre = pf2[m0n + tid];
            int wd = m0n >> 5;
            abl0 = ab_lo[wd]; abl1 = ab_lo[wd + 1];
            abh0 = ab_hi[wd]; abh1 = ab_hi[wd + 1];
        }

        #pragma unroll
        for (int k = 0; k < 8; k++) {
            const int ma = k * 8 + (l & 3);
            float4 fa = f2S[ma];
            float4 fb = f2S[ma + 4];
            u32 wlo = (k < 4) ? wl0 : wl1;
            u32 whi = (k < 4) ? wh0 : wh1;
            int ba = (k & 3) * 8 + (l & 3);
            float p00 = p_of(p1lo, fa, (wlo >> ba) & 1u);
            float p10 = p_of(p1hi, fa, (whi >> ba) & 1u);
            float p01 = p_of(p1lo, fb, (wlo >> (ba + 4)) & 1u);
            float p11 = p_of(p1hi, fb, (whi >> (ba + 4)) & 1u);
            Slo += p00 + p01;
            Shi += p10 + p11;
            u32 a0 = tf32r(p00), a1 = tf32r(p10), a2 = tf32r(p01), a3 = tf32r(p11);
            #pragma unroll
            for (int t = 0; t < 8; t++) {
                u32 b0 = __float_as_uint(WhS[ma    ][8*t + (l >> 2)]);
                u32 b1 = __float_as_uint(WhS[ma + 4][8*t + (l >> 2)]);
                mma_tf32(c[t], a0, a1, a2, a3, b0, b1);
            }
        }
    }

    // reduce row sums across the 4 lanes sharing each row
    Slo += __shfl_xor_sync(0xffffffffu, Slo, 1);
    Slo += __shfl_xor_sync(0xffffffffu, Slo, 2);
    Shi += __shfl_xor_sync(0xffffffffu, Shi, 1);
    Shi += __shfl_xor_sync(0xffffffffu, Shi, 2);
    if ((l & 3) == 0) { sS[rlo] = Slo; sS[rhi] = Shi; }
    __syncthreads();
    const float ilo = 1.0f / sS[rlo];
    const float ihi = 1.0f / sS[rhi];

    float* dlo = g_hcat + ((size_t)g * NN + nbase + rlo) * (NHEADS*NHID) + h * NHID;
    float* dhi = g_hcat + ((size_t)g * NN + nbase + rhi) * (NHEADS*NHID) + h * NHID;
    #pragma unroll
    for (int t = 0; t < 8; t++) {
        int col = 8 * t + 2 * (l & 3);
        float2 v;
        v.x = eluf(c[t][0] * ilo); v.y = eluf(c[t][1] * ilo);
        *(float2*)(dlo + col) = v;
        v.x = eluf(c[t][2] * ihi); v.y = eluf(c[t][3] * ihi);
        *(float2*)(dhi + col) = v;
    }
}

// ---------------------------------------------------------------------------
// K4: xi = elu(hcat . W_int + b)
// ---------------------------------------------------------------------------
__global__ void k_xi(const float* __restrict__ W_int, const float* __restrict__ b_int)
{
    __shared__ float Ws[NCLASS * 256];
    __shared__ float bs[NCLASS];
    const int tid = threadIdx.x, w = tid >> 5, lane = tid & 31;
    #pragma unroll
    for (int j = 0; j < 4; j++)
        *(float4*)&Ws[tid * 4 + j * 1024] = *(const float4*)(W_int + tid * 4 + j * 1024);
    if (tid < NCLASS) bs[tid] = b_int[tid];
    __syncthreads();

    long idx = (long)blockIdx.x * 8 + w;
    int g = (int)(idx / NN);
    int n = (int)(idx % NN);
    const float* hrow = g_hcat + ((size_t)g * NN + n) * 256;
    float v[8];
    #pragma unroll
    for (int j = 0; j < 8; j++) v[j] = hrow[lane + 32 * j];

    for (int c = 0; c < NCLASS; c++) {
        const float* wc = Ws + c * 256;
        float s = 0.f;
        #pragma unroll
        for (int j = 0; j < 8; j++) s += v[j] * wc[lane + 32 * j];
        #pragma unroll
        for (int o = 16; o >= 1; o >>= 1) s += __shfl_xor_sync(0xffffffffu, s, o);
        if (lane == 0) {
            float t = s + bs[c];
            t = (t > 0.f) ? t : expm1f(t);
            g_xib[(size_t)n * (NGRAPH*NCLASS) + g * NCLASS + c] = t;
        }
    }
}

// ---------------------------------------------------------------------------
// K5: out = log_softmax(xib @ W_fus^T + b_fus)
// ---------------------------------------------------------------------------
__global__ void k_out(const float* __restrict__ W_fus, const float* __restrict__ b_fus,
                      float* __restrict__ out)
{
    __shared__ float Wf[NCLASS * 48];
    __shared__ float bf[NCLASS];
    const int tid = threadIdx.x;
    for (int i = tid; i < NCLASS * 48; i += 256) Wf[i] = W_fus[i];
    if (tid < NCLASS) bf[tid] = b_fus[tid];
    __syncthreads();

    int n = blockIdx.x * 256 + tid;
    const float* xr = g_xib + (size_t)n * 48;
    float xv[48];
    #pragma unroll
    for (int j = 0; j < 48; j++) xv[j] = xr[j];

    float o[NCLASS];
    float mx = -FLT_MAX;
    #pragma unroll
    for (int c = 0; c < NCLASS; c++) {
        float s = bf[c];
        #pragma unroll
        for (int j = 0; j < 48; j++) s += xv[j] * Wf[c * 48 + j];
        o[c] = s;
        mx = fmaxf(mx, s);
    }
    float sum = 0.f;
    #pragma unroll
    for (int c = 0; c < NCLASS; c++) sum += expf(o[c] - mx);
    float lse = mx + logf(sum);
    float* dst = out + (size_t)n * NCLASS;
    #pragma unroll
    for (int c = 0; c < NCLASS; c++) dst[c] = o[c] - lse;
}

// ---------------------------------------------------------------------------
// K6: l1 = mean |W_fus|
// ---------------------------------------------------------------------------
__global__ void k_l1(const float* __restrict__ W_fus, float* __restrict__ out, int out_size)
{
    __shared__ float red[256];
    int tid = threadIdx.x;
    float s = 0.f;
    for (int i = tid; i < NCLASS * 48; i += 256) s += fabsf(W_fus[i]);
    red[tid] = s;
    __syncthreads();
    for (int o = 128; o >= 1; o >>= 1) {
        if (tid < o) red[tid] += red[tid + o];
        __syncthreads();
    }
    if (tid == 0) {
        float l1 = red[0] / (float)(NCLASS * 48);
        for (int i = NN * NCLASS; i < out_size; i++) out[i] = l1;
    }
}

extern "C" void kernel_launch(void* const* d_in, const int* in_sizes, int n_in,
                              void* d_out, int out_size)
{
    const float* x     = (const float*)d_in[0];
    const int*   adj   = (const int*)  d_in[1];
    const float* W     = (const float*)d_in[2];
    const float* a     = (const float*)d_in[3];
    const float* W_int = (const float*)d_in[4];
    const float* b_int = (const float*)d_in[5];
    const float* W_fus = (const float*)d_in[6];
    const float* b_fus = (const float*)d_in[7];
    float* out = (float*)d_out;

    k_pack <<<NGRAPH * NN / 8, 256>>>(adj);
    k_wh   <<<dim3(NN/64, GH), 256>>>(x, W);
    k_f12  <<<GH * NN / 8, 256>>>(a);
    k_att_mma<<<NGRAPH * NHEADS * (NN/128), 256>>>();
    k_xi   <<<NGRAPH * NN / 8, 256>>>(W_int, b_int);
    k_out  <<<NN/256, 256>>>(W_fus, b_fus, out);
    k_l1   <<<1, 256>>>(W_fus, out, out_size);
}

// round 8
// speedup vs baseline: 3.6056x; 1.2061x over previous
#include <cuda_runtime.h>
#include <cuda_fp16.h>
#include <math.h>
#include <float.h>

#define NN 3072
#define FIN 512
#define NHID 64
#define NHEADS 4
#define NGRAPH 3
#define GH (NGRAPH*NHEADS)
#define NCLASS 16
#define ALPHA 0.2f

typedef unsigned long long u64;
typedef unsigned int u32;

// ---------------- packed fp32x2 helpers (FFMA2) ----------------
__device__ __forceinline__ u64 ffma2(u64 a, u64 b, u64 c) {
    u64 d; asm("fma.rn.f32x2 %0, %1, %2, %3;" : "=l"(d) : "l"(a), "l"(b), "l"(c)); return d;
}
__device__ __forceinline__ u64 bcast2(float x) {
    u64 d; asm("mov.b64 %0, {%1, %1};" : "=l"(d) : "f"(x)); return d;
}
__device__ __forceinline__ float2 unpack2(u64 v) {
    float2 r; asm("mov.b64 {%0, %1}, %2;" : "=f"(r.x), "=f"(r.y) : "l"(v)); return r;
}
// pack two floats into fp16x2 (lo = a, hi = b)
__device__ __forceinline__ u32 packh2(float a, float b) {
    u32 d; asm("cvt.rn.f16x2.f32 %0, %1, %2;" : "=r"(d) : "f"(b), "f"(a)); return d;
}
// warp mma m16n8k16 fp16 (portable PTX since sm_80)
__device__ __forceinline__ void mma_f16(float* c, u32 a0, u32 a1, u32 a2, u32 a3,
                                        u32 b0, u32 b1) {
    asm volatile(
        "mma.sync.aligned.m16n8k16.row.col.f32.f16.f16.f32 "
        "{%0,%1,%2,%3}, {%4,%5,%6,%7}, {%8,%9}, {%0,%1,%2,%3};"
        : "+f"(c[0]), "+f"(c[1]), "+f"(c[2]), "+f"(c[3])
        : "r"(a0), "r"(a1), "r"(a2), "r"(a3), "r"(b0), "r"(b1));
}

// ---------------- device scratch ----------------
__device__ float  g_Wh[GH * NN * NHID];          // [gh][n][o]
__device__ float4 g_pf1[GH * NN];                // (f1, exp(f1), exp(a*f1), 0)
__device__ float4 g_pf2[GH * NN];                // (f2, exp(f2), exp(a*f2), 0)
__device__ u32    g_abits[NGRAPH * NN * (NN/32)];// [g][n][m/32]
__device__ float  g_hcat[NGRAPH * NN * (NHEADS*NHID)];
__device__ float  g_xib[NN * (NGRAPH*NCLASS)];

// ---------------------------------------------------------------------------
// K1: Wh = x @ W  (FFMA2 64x64 tiles)
// ---------------------------------------------------------------------------
__global__ void k_wh(const float* __restrict__ x, const float* __restrict__ W)
{
    __shared__ float As[32][65];
    __shared__ float Bs[32][68];
    const int gh = blockIdx.y;
    const int nbase = blockIdx.x * 64;
    const float* Wg = W + (size_t)gh * FIN * NHID;
    const int tid = threadIdx.x;
    const int tx = tid & 15, ty = tid >> 4;
    u64 acc[4][2];
    #pragma unroll
    for (int i = 0; i < 4; i++) { acc[i][0] = bcast2(0.f); acc[i][1] = bcast2(0.f); }

    for (int k0 = 0; k0 < FIN; k0 += 32) {
        {
            int r  = tid >> 3;
            int c4 = (tid & 7) * 4;
            float4 v0 = *(const float4*)(x + (size_t)(nbase + r)      * FIN + k0 + c4);
            float4 v1 = *(const float4*)(x + (size_t)(nbase + r + 32) * FIN + k0 + c4);
            As[c4+0][r]    = v0.x; As[c4+1][r]    = v0.y; As[c4+2][r]    = v0.z; As[c4+3][r]    = v0.w;
            As[c4+0][r+32] = v1.x; As[c4+1][r+32] = v1.y; As[c4+2][r+32] = v1.z; As[c4+3][r+32] = v1.w;
        }
        {
            int rb = tid >> 4;
            int cb = (tid & 15) * 4;
            *(float4*)&Bs[rb][cb]    = *(const float4*)(Wg + (size_t)(k0 + rb)      * NHID + cb);
            *(float4*)&Bs[rb+16][cb] = *(const float4*)(Wg + (size_t)(k0 + rb + 16) * NHID + cb);
        }
        __syncthreads();
        #pragma unroll
        for (int k = 0; k < 32; k++) {
            u64 b01 = *(const u64*)&Bs[k][tx*4];
            u64 b23 = *(const u64*)&Bs[k][tx*4 + 2];
            #pragma unroll
            for (int i = 0; i < 4; i++) {
                u64 pa = bcast2(As[k][ty*4 + i]);
                acc[i][0] = ffma2(pa, b01, acc[i][0]);
                acc[i][1] = ffma2(pa, b23, acc[i][1]);
            }
        }
        __syncthreads();
    }
    float* out = g_Wh + ((size_t)gh * NN + nbase) * NHID;
    #pragma unroll
    for (int i = 0; i < 4; i++) {
        float2 lo = unpack2(acc[i][0]);
        float2 hi = unpack2(acc[i][1]);
        float4 v; v.x = lo.x; v.y = lo.y; v.z = hi.x; v.w = hi.y;
        *(float4*)(out + (size_t)(ty*4 + i) * NHID + tx*4) = v;
    }
}

// ---------------------------------------------------------------------------
// K1b: pack adjacency into bitmask
// ---------------------------------------------------------------------------
__global__ void k_pack(const int* __restrict__ adj)
{
    int w = threadIdx.x >> 5, lane = threadIdx.x & 31;
    long idx = (long)blockIdx.x * 8 + w;     // 0 .. NGRAPH*NN-1
    const int* ar = adj + (size_t)idx * NN;
    u32* dst = g_abits + (size_t)idx * (NN/32);
    for (int w0 = 0; w0 < NN/32; w0++) {
        int v = ar[w0 * 32 + lane];
        u32 b = __ballot_sync(0xffffffffu, v > 0);
        if (lane == 0) dst[w0] = b;
    }
}

// ---------------------------------------------------------------------------
// K2: f1/f2 dots + separated exponentials
// ---------------------------------------------------------------------------
__global__ void k_f12(const float* __restrict__ a)
{
    int tid = threadIdx.x, w = tid >> 5, lane = tid & 31;
    long idx = (long)blockIdx.x * 8 + w;
    int gh = (int)(idx / NN);
    int n  = (int)(idx % NN);
    const float* whr = g_Wh + ((size_t)gh * NN + n) * NHID;
    const float* ag  = a + (size_t)gh * 2 * NHID;
    float w0 = whr[lane], w1 = whr[lane + 32];
    float s1 = w0 * ag[lane]      + w1 * ag[lane + 32];
    float s2 = w0 * ag[64 + lane] + w1 * ag[64 + lane + 32];
    #pragma unroll
    for (int o = 16; o >= 1; o >>= 1) {
        s1 += __shfl_xor_sync(0xffffffffu, s1, o);
        s2 += __shfl_xor_sync(0xffffffffu, s2, o);
    }
    if (lane == 0) {
        float4 v1; v1.x = s1; v1.y = __expf(s1); v1.z = __expf(ALPHA * s1); v1.w = 0.f;
        float4 v2; v2.x = s2; v2.y = __expf(s2); v2.z = __expf(ALPHA * s2); v2.w = 0.f;
        g_pf1[(size_t)gh * NN + n] = v1;
        g_pf2[(size_t)gh * NN + n] = v2;
    }
}

// ---------------------------------------------------------------------------
// K3: attention via warp-mma fp16 m16n8k16, exp-separated p, shift-0 softmax.
// 256 thr = 8 warps, 128 rows/CTA. 48 chunks of 64 m.
// B tile in smem as fp16x2 m-pairs: WhP[mpair][o] (u32), stride 72 u32.
// ---------------------------------------------------------------------------
__device__ __forceinline__ float p_of(const float4 p1, const float4 f2v, u32 bit) {
    float t = p1.x + f2v.x;
    float v = (t > 0.f) ? (p1.y * f2v.y) : (p1.z * f2v.z);
    return bit ? v : 0.f;
}
__device__ __forceinline__ float eluf(float v) {
    return (v > 0.f) ? v : expm1f(v);
}

#define WP_STRIDE 72   // u32 per mpair row (64 used + 8 pad -> conflict-free frag loads)

__global__ void __launch_bounds__(256, 2) k_att_mma()
{
    __shared__ u32    WhP[32 * WP_STRIDE];   // 9216 B: fp16x2 (m,m+1) per o
    __shared__ float4 f2S[64];               // (f2, E2, E2a, -)
    __shared__ float  sS[128];

    const int tid = threadIdx.x, w = tid >> 5, l = tid & 31;
    const int bid  = blockIdx.x;
    const int tile = bid % 24;
    const int h    = (bid / 24) % NHEADS;
    const int g    = bid / (24 * NHEADS);
    const int gh   = g * NHEADS + h;
    const int nbase = tile * 128;

    const int rlo = w * 16 + (l >> 2);   // local row (0..127)
    const int rhi = rlo + 8;

    const float4 p1lo = g_pf1[(size_t)gh * NN + nbase + rlo];
    const float4 p1hi = g_pf1[(size_t)gh * NN + nbase + rhi];
    const float4* pf2 = g_pf2 + (size_t)gh * NN;
    const u32* ab_lo  = g_abits + ((size_t)g * NN + nbase + rlo) * (NN/32);
    const u32* ab_hi  = g_abits + ((size_t)g * NN + nbase + rhi) * (NN/32);
    const float* Whg  = g_Wh + (size_t)gh * NN * NHID;

    float c[8][4];
    #pragma unroll
    for (int t = 0; t < 8; t++) { c[t][0]=0.f; c[t][1]=0.f; c[t][2]=0.f; c[t][3]=0.f; }
    float Slo = 0.f, Shi = 0.f;

    // staging geometry: thread covers m-pair (2*mp, 2*mp+1), o = og..og+7
    const int mp = tid >> 3;            // 0..31
    const int og = (tid & 7) * 8;       // 0..56

    // prefetch chunk 0
    float4 wpre[4]; float4 fpre = make_float4(0,0,0,0);
    u32 abl0, abl1, abh0, abh1;
    {
        const float* r0 = Whg + (size_t)(2*mp)     * NHID + og;
        const float* r1 = Whg + (size_t)(2*mp + 1) * NHID + og;
        wpre[0] = *(const float4*)(r0);
        wpre[1] = *(const float4*)(r0 + 4);
        wpre[2] = *(const float4*)(r1);
        wpre[3] = *(const float4*)(r1 + 4);
        if (tid < 64) fpre = pf2[tid];
        abl0 = ab_lo[0]; abl1 = ab_lo[1];
        abh0 = ab_hi[0]; abh1 = ab_hi[1];
    }

    for (int i = 0; i < NN/64; i++) {
        __syncthreads();
        {   // store staged chunk as fp16x2 m-pairs
            u32 pk[8];
            pk[0] = packh2(wpre[0].x, wpre[2].x);
            pk[1] = packh2(wpre[0].y, wpre[2].y);
            pk[2] = packh2(wpre[0].z, wpre[2].z);
            pk[3] = packh2(wpre[0].w, wpre[2].w);
            pk[4] = packh2(wpre[1].x, wpre[3].x);
            pk[5] = packh2(wpre[1].y, wpre[3].y);
            pk[6] = packh2(wpre[1].z, wpre[3].z);
            pk[7] = packh2(wpre[1].w, wpre[3].w);
            *(uint4*)&WhP[mp * WP_STRIDE + og]     = *(uint4*)&pk[0];
            *(uint4*)&WhP[mp * WP_STRIDE + og + 4] = *(uint4*)&pk[4];
            if (tid < 64) f2S[tid] = fpre;
        }
        const u32 wl0 = abl0, wl1 = abl1, wh0 = abh0, wh1 = abh1;
        __syncthreads();

        if (i + 1 < NN/64) {   // prefetch next chunk into regs
            int m0n = (i + 1) * 64;
            const float* r0 = Whg + (size_t)(m0n + 2*mp)     * NHID + og;
            const float* r1 = Whg + (size_t)(m0n + 2*mp + 1) * NHID + og;
            wpre[0] = *(const float4*)(r0);
            wpre[1] = *(const float4*)(r0 + 4);
            wpre[2] = *(const float4*)(r1);
            wpre[3] = *(const float4*)(r1 + 4);
            if (tid < 64) fpre = pf2[m0n + tid];
            int wd = m0n >> 5;
            abl0 = ab_lo[wd]; abl1 = ab_lo[wd + 1];
            abh0 = ab_hi[wd]; abh1 = ab_hi[wd + 1];
        }

        #pragma unroll
        for (int kk = 0; kk < 4; kk++) {          // 16 m's per k-iter
            const int m0 = kk * 16 + 2 * (l & 3); // this thread's k0 in chunk
            float4 fA0 = f2S[m0];
            float4 fA1 = f2S[m0 + 1];
            float4 fB0 = f2S[m0 + 8];
            float4 fB1 = f2S[m0 + 9];
            const u32 wlo = (kk < 2) ? wl0 : wl1;
            const u32 whi = (kk < 2) ? wh0 : wh1;
            const int bb = (kk & 1) * 16 + 2 * (l & 3);
            float pA0 = p_of(p1lo, fA0, (wlo >> bb) & 1u);
            float pA1 = p_of(p1lo, fA1, (wlo >> (bb+1)) & 1u);
            float pB0 = p_of(p1lo, fB0, (wlo >> (bb+8)) & 1u);
            float pB1 = p_of(p1lo, fB1, (wlo >> (bb+9)) & 1u);
            float qA0 = p_of(p1hi, fA0, (whi >> bb) & 1u);
            float qA1 = p_of(p1hi, fA1, (whi >> (bb+1)) & 1u);
            float qB0 = p_of(p1hi, fB0, (whi >> (bb+8)) & 1u);
            float qB1 = p_of(p1hi, fB1, (whi >> (bb+9)) & 1u);
            Slo += (pA0 + pA1) + (pB0 + pB1);
            Shi += (qA0 + qA1) + (qB0 + qB1);
            u32 a0 = packh2(pA0, pA1);
            u32 a1 = packh2(qA0, qA1);
            u32 a2 = packh2(pB0, pB1);
            u32 a3 = packh2(qB0, qB1);
            const int mpb = kk * 8 + (l & 3);       // mpair row for b0
            const u32* base0 = &WhP[mpb * WP_STRIDE + (l >> 2)];
            #pragma unroll
            for (int t = 0; t < 8; t++) {
                u32 b0 = base0[8 * t];
                u32 b1 = base0[4 * WP_STRIDE + 8 * t];
                mma_f16(c[t], a0, a1, a2, a3, b0, b1);
            }
        }
    }

    // reduce row sums across the 4 lanes sharing each row
    Slo += __shfl_xor_sync(0xffffffffu, Slo, 1);
    Slo += __shfl_xor_sync(0xffffffffu, Slo, 2);
    Shi += __shfl_xor_sync(0xffffffffu, Shi, 1);
    Shi += __shfl_xor_sync(0xffffffffu, Shi, 2);
    if ((l & 3) == 0) { sS[rlo] = Slo; sS[rhi] = Shi; }
    __syncthreads();
    const float ilo = 1.0f / sS[rlo];
    const float ihi = 1.0f / sS[rhi];

    float* dlo = g_hcat + ((size_t)g * NN + nbase + rlo) * (NHEADS*NHID) + h * NHID;
    float* dhi = g_hcat + ((size_t)g * NN + nbase + rhi) * (NHEADS*NHID) + h * NHID;
    #pragma unroll
    for (int t = 0; t < 8; t++) {
        int col = 8 * t + 2 * (l & 3);
        float2 v;
        v.x = eluf(c[t][0] * ilo); v.y = eluf(c[t][1] * ilo);
        *(float2*)(dlo + col) = v;
        v.x = eluf(c[t][2] * ihi); v.y = eluf(c[t][3] * ihi);
        *(float2*)(dhi + col) = v;
    }
}

// ---------------------------------------------------------------------------
// K4: xi = elu(hcat . W_int + b)
// ---------------------------------------------------------------------------
__global__ void k_xi(const float* __restrict__ W_int, const float* __restrict__ b_int)
{
    __shared__ float Ws[NCLASS * 256];
    __shared__ float bs[NCLASS];
    const int tid = threadIdx.x, w = tid >> 5, lane = tid & 31;
    #pragma unroll
    for (int j = 0; j < 4; j++)
        *(float4*)&Ws[tid * 4 + j * 1024] = *(const float4*)(W_int + tid * 4 + j * 1024);
    if (tid < NCLASS) bs[tid] = b_int[tid];
    __syncthreads();

    long idx = (long)blockIdx.x * 8 + w;
    int g = (int)(idx / NN);
    int n = (int)(idx % NN);
    const float* hrow = g_hcat + ((size_t)g * NN + n) * 256;
    float v[8];
    #pragma unroll
    for (int j = 0; j < 8; j++) v[j] = hrow[lane + 32 * j];

    for (int c = 0; c < NCLASS; c++) {
        const float* wc = Ws + c * 256;
        float s = 0.f;
        #pragma unroll
        for (int j = 0; j < 8; j++) s += v[j] * wc[lane + 32 * j];
        #pragma unroll
        for (int o = 16; o >= 1; o >>= 1) s += __shfl_xor_sync(0xffffffffu, s, o);
        if (lane == 0) {
            float t = s + bs[c];
            t = (t > 0.f) ? t : expm1f(t);
            g_xib[(size_t)n * (NGRAPH*NCLASS) + g * NCLASS + c] = t;
        }
    }
}

// ---------------------------------------------------------------------------
// K5: out = log_softmax(xib @ W_fus^T + b_fus)
// ---------------------------------------------------------------------------
__global__ void k_out(const float* __restrict__ W_fus, const float* __restrict__ b_fus,
                      float* __restrict__ out)
{
    __shared__ float Wf[NCLASS * 48];
    __shared__ float bf[NCLASS];
    const int tid = threadIdx.x;
    for (int i = tid; i < NCLASS * 48; i += 256) Wf[i] = W_fus[i];
    if (tid < NCLASS) bf[tid] = b_fus[tid];
    __syncthreads();

    int n = blockIdx.x * 256 + tid;
    const float* xr = g_xib + (size_t)n * 48;
    float xv[48];
    #pragma unroll
    for (int j = 0; j < 48; j++) xv[j] = xr[j];

    float o[NCLASS];
    float mx = -FLT_MAX;
    #pragma unroll
    for (int c = 0; c < NCLASS; c++) {
        float s = bf[c];
        #pragma unroll
        for (int j = 0; j < 48; j++) s += xv[j] * Wf[c * 48 + j];
        o[c] = s;
        mx = fmaxf(mx, s);
    }
    float sum = 0.f;
    #pragma unroll
    for (int c = 0; c < NCLASS; c++) sum += expf(o[c] - mx);
    float lse = mx + logf(sum);
    float* dst = out + (size_t)n * NCLASS;
    #pragma unroll
    for (int c = 0; c < NCLASS; c++) dst[c] = o[c] - lse;
}

// ---------------------------------------------------------------------------
// K6: l1 = mean |W_fus|
// ---------------------------------------------------------------------------
__global__ void k_l1(const float* __restrict__ W_fus, float* __restrict__ out, int out_size)
{
    __shared__ float red[256];
    int tid = threadIdx.x;
    float s = 0.f;
    for (int i = tid; i < NCLASS * 48; i += 256) s += fabsf(W_fus[i]);
    red[tid] = s;
    __syncthreads();
    for (int o = 128; o >= 1; o >>= 1) {
        if (tid < o) red[tid] += red[tid + o];
        __syncthreads();
    }
    if (tid == 0) {
        float l1 = red[0] / (float)(NCLASS * 48);
        for (int i = NN * NCLASS; i < out_size; i++) out[i] = l1;
    }
}

extern "C" void kernel_launch(void* const* d_in, const int* in_sizes, int n_in,
                              void* d_out, int out_size)
{
    const float* x     = (const float*)d_in[0];
    const int*   adj   = (const int*)  d_in[1];
    const float* W     = (const float*)d_in[2];
    const float* a     = (const float*)d_in[3];
    const float* W_int = (const float*)d_in[4];
    const float* b_int = (const float*)d_in[5];
    const float* W_fus = (const float*)d_in[6];
    const float* b_fus = (const float*)d_in[7];
    float* out = (float*)d_out;

    k_pack <<<NGRAPH * NN / 8, 256>>>(adj);
    k_wh   <<<dim3(NN/64, GH), 256>>>(x, W);
    k_f12  <<<GH * NN / 8, 256>>>(a);
    k_att_mma<<<NGRAPH * NHEADS * (NN/128), 256>>>();
    k_xi   <<<NGRAPH * NN / 8, 256>>>(W_int, b_int);
    k_out  <<<NN/256, 256>>>(W_fus, b_fus, out);
    k_l1   <<<1, 256>>>(W_fus, out, out_size);
}

// round 10
// speedup vs baseline: 4.9506x; 1.3730x over previous
#include <cuda_runtime.h>
#include <cuda_fp16.h>
#include <math.h>
#include <float.h>

#define NN 3072
#define FIN 512
#define NHID 64
#define NHEADS 4
#define NGRAPH 3
#define GH (NGRAPH*NHEADS)
#define NCLASS 16
#define ALPHA 0.2f

typedef unsigned long long u64;
typedef unsigned int u32;

// pack two floats into fp16x2 (lo = a, hi = b)
__device__ __forceinline__ u32 packh2(float a, float b) {
    u32 d; asm("cvt.rn.f16x2.f32 %0, %1, %2;" : "=r"(d) : "f"(b), "f"(a)); return d;
}
__device__ __forceinline__ __half2 U2H(u32 u) { return *reinterpret_cast<__half2*>(&u); }
__device__ __forceinline__ u32 H2U(__half2 h) { return *reinterpret_cast<u32*>(&h); }

// warp mma m16n8k16 fp16 (portable PTX since sm_80)
__device__ __forceinline__ void mma_f16(float* c, u32 a0, u32 a1, u32 a2, u32 a3,
                                        u32 b0, u32 b1) {
    asm volatile(
        "mma.sync.aligned.m16n8k16.row.col.f32.f16.f16.f32 "
        "{%0,%1,%2,%3}, {%4,%5,%6,%7}, {%8,%9}, {%0,%1,%2,%3};"
        : "+f"(c[0]), "+f"(c[1]), "+f"(c[2]), "+f"(c[3])
        : "r"(a0), "r"(a1), "r"(a2), "r"(a3), "r"(b0), "r"(b1));
}

// ---------------- device scratch ----------------
__device__ float  g_Wh[GH * NN * NHID];          // [gh][n][o] fp32
__device__ u32    g_xp [NN * (FIN/2)];           // x as fp16 (f,f+1) pairs [n][fp]
__device__ u32    g_wfp[GH * (FIN/2) * NHID];    // W as fp16 f-pairs [gh][fp][o]
__device__ u32    g_whp[GH * (NN/2) * NHID];     // Wh as fp16 (n,n+1) pairs [gh][np][o]
__device__ float4 g_pf1[GH * NN];                // (f1, exp(f1), exp(a*f1), 0)
__device__ float4 g_pf2[GH * NN];                // (f2, exp(f2), exp(a*f2), 0)
__device__ uint4  g_f2h[GH * (NN/2)];            // fp16 pairs: (f2p, E2p, E2ap, 0)
__device__ u32    g_abits[NGRAPH * NN * (NN/32)];// [g][n][m/32]
__device__ float  g_hcat[NGRAPH * NN * (NHEADS*NHID)];
__device__ float  g_xib[NN * (NGRAPH*NCLASS)];

#define XP_TOTAL (NN * (FIN/2))                  // 786432
#define WP_TOTAL (GH * (FIN/2) * NHID)           // 196608

// ---------------------------------------------------------------------------
// K0: convert x and W to fp16 pair layouts (one elem per thread)
// ---------------------------------------------------------------------------
__global__ void k_cvt(const float* __restrict__ x, const float* __restrict__ W)
{
    int idx = blockIdx.x * blockDim.x + threadIdx.x;
    if (idx < XP_TOTAL) {
        int n = idx >> 8, fp = idx & 255;      // FIN/2 = 256
        const float* src = x + (size_t)n * FIN + 2 * fp;
        g_xp[idx] = packh2(src[0], src[1]);
    } else {
        int j = idx - XP_TOTAL;
        if (j < WP_TOTAL) {
            int gh = j / ((FIN/2) * NHID);
            int r  = j % ((FIN/2) * NHID);
            int fp = r >> 6, o = r & 63;
            const float* src = W + ((size_t)gh * FIN + 2 * fp) * NHID + o;
            g_wfp[j] = packh2(src[0], src[NHID]);
        }
    }
}

// ---------------------------------------------------------------------------
// K1: Wh = x @ W via fp16 mma. CTA = 128 n-rows x 64 o, one gh. 8 warps.
// ---------------------------------------------------------------------------
#define AX_STRIDE 36   // u32 per n-row (32 fpairs + pad)
#define WF_STRIDE 72   // u32 per fpair-row (64 o + pad)

__global__ void __launch_bounds__(256, 2) k_wh_mma()
{
    __shared__ u32 AxS[128 * AX_STRIDE];   // 18.4 KB
    __shared__ u32 WfS[32 * WF_STRIDE];    // 9.2 KB

    const int tid = threadIdx.x, w = tid >> 5, l = tid & 31;
    const int nbase = blockIdx.x * 128;
    const int gh = blockIdx.y;
    const int rlo = w * 16 + (l >> 2);
    const int rhi = rlo + 8;

    float c[8][4];
    #pragma unroll
    for (int t = 0; t < 8; t++) { c[t][0]=0.f; c[t][1]=0.f; c[t][2]=0.f; c[t][3]=0.f; }

    // staging geometry
    const int an  = tid >> 1;                 // A: n row 0..127
    const int afp = (tid & 1) * 16;           // A: fp base 0/16
    const int bfp = tid >> 3;                 // B: fpair row 0..31
    const int bog = (tid & 7) * 8;            // B: o base

    uint4 apre[4]; uint4 bpre[2];
    {
        const uint4* as = (const uint4*)(g_xp + (size_t)(nbase + an) * (FIN/2) + afp);
        #pragma unroll
        for (int j = 0; j < 4; j++) apre[j] = as[j];
        const uint4* bs = (const uint4*)(g_wfp + ((size_t)gh * (FIN/2) + bfp) * NHID + bog);
        bpre[0] = bs[0]; bpre[1] = bs[1];
    }

    for (int ch = 0; ch < FIN/64; ch++) {
        __syncthreads();
        {
            uint4* ad = (uint4*)&AxS[an * AX_STRIDE + afp];
            #pragma unroll
            for (int j = 0; j < 4; j++) ad[j] = apre[j];
            uint4* bd = (uint4*)&WfS[bfp * WF_STRIDE + bog];
            bd[0] = bpre[0]; bd[1] = bpre[1];
        }
        __syncthreads();
        if (ch + 1 < FIN/64) {
            const uint4* as = (const uint4*)(g_xp + (size_t)(nbase + an) * (FIN/2) + (ch+1)*32 + afp);
            #pragma unroll
            for (int j = 0; j < 4; j++) apre[j] = as[j];
            const uint4* bs = (const uint4*)(g_wfp + ((size_t)gh * (FIN/2) + (ch+1)*32 + bfp) * NHID + bog);
            bpre[0] = bs[0]; bpre[1] = bs[1];
        }
        #pragma unroll
        for (int kk = 0; kk < 4; kk++) {
            u32 a0 = AxS[rlo * AX_STRIDE + kk*8 + (l & 3)];
            u32 a1 = AxS[rhi * AX_STRIDE + kk*8 + (l & 3)];
            u32 a2 = AxS[rlo * AX_STRIDE + kk*8 + 4 + (l & 3)];
            u32 a3 = AxS[rhi * AX_STRIDE + kk*8 + 4 + (l & 3)];
            const u32* bb0 = &WfS[(kk*8 + (l & 3)) * WF_STRIDE + (l >> 2)];
            #pragma unroll
            for (int t = 0; t < 8; t++) {
                u32 b0 = bb0[8 * t];
                u32 b1 = bb0[4 * WF_STRIDE + 8 * t];
                mma_f16(c[t], a0, a1, a2, a3, b0, b1);
            }
        }
    }

    float* dlo = g_Wh + ((size_t)gh * NN + nbase + rlo) * NHID;
    float* dhi = g_Wh + ((size_t)gh * NN + nbase + rhi) * NHID;
    #pragma unroll
    for (int t = 0; t < 8; t++) {
        int col = 8 * t + 2 * (l & 3);
        float2 v;
        v.x = c[t][0]; v.y = c[t][1];
        *(float2*)(dlo + col) = v;
        v.x = c[t][2]; v.y = c[t][3];
        *(float2*)(dhi + col) = v;
    }
}

// ---------------------------------------------------------------------------
// K1b: pack adjacency into bitmask
// ---------------------------------------------------------------------------
__global__ void k_pack(const int* __restrict__ adj)
{
    int w = threadIdx.x >> 5, lane = threadIdx.x & 31;
    long idx = (long)blockIdx.x * 8 + w;
    const int* ar = adj + (size_t)idx * NN;
    u32* dst = g_abits + (size_t)idx * (NN/32);
    for (int w0 = 0; w0 < NN/32; w0++) {
        int v = ar[w0 * 32 + lane];
        u32 b = __ballot_sync(0xffffffffu, v > 0);
        if (lane == 0) dst[w0] = b;
    }
}

// ---------------------------------------------------------------------------
// K2: f1/f2 dots + separated exponentials (from fp32 Wh)
// ---------------------------------------------------------------------------
__global__ void k_f12(const float* __restrict__ a)
{
    int tid = threadIdx.x, w = tid >> 5, lane = tid & 31;
    long idx = (long)blockIdx.x * 8 + w;
    int gh = (int)(idx / NN);
    int n  = (int)(idx % NN);
    const float* whr = g_Wh + ((size_t)gh * NN + n) * NHID;
    const float* ag  = a + (size_t)gh * 2 * NHID;
    float w0 = whr[lane], w1 = whr[lane + 32];
    float s1 = w0 * ag[lane]      + w1 * ag[lane + 32];
    float s2 = w0 * ag[64 + lane] + w1 * ag[64 + lane + 32];
    #pragma unroll
    for (int o = 16; o >= 1; o >>= 1) {
        s1 += __shfl_xor_sync(0xffffffffu, s1, o);
        s2 += __shfl_xor_sync(0xffffffffu, s2, o);
    }
    if (lane == 0) {
        float4 v1; v1.x = s1; v1.y = __expf(s1); v1.z = __expf(ALPHA * s1); v1.w = 0.f;
        float4 v2; v2.x = s2; v2.y = __expf(s2); v2.z = __expf(ALPHA * s2); v2.w = 0.f;
        g_pf1[(size_t)gh * NN + n] = v1;
        g_pf2[(size_t)gh * NN + n] = v2;
    }
}

// ---------------------------------------------------------------------------
// K2b: pack Wh fp32 -> fp16 (n,n+1) pairs  [gh][np][o]
// one uint4 (4 o's) per thread
// ---------------------------------------------------------------------------
__global__ void k_whp()
{
    int idx = blockIdx.x * blockDim.x + threadIdx.x;   // 0 .. GH*1536*16-1
    int flat = idx >> 4;            // gh*1536 + np
    int o4 = (idx & 15) * 4;
    const float* r0 = g_Wh + ((size_t)flat * 2) * NHID + o4;
    const float* r1 = r0 + NHID;
    float4 a = *(const float4*)r0;
    float4 b = *(const float4*)r1;
    uint4 v;
    v.x = packh2(a.x, b.x);
    v.y = packh2(a.y, b.y);
    v.z = packh2(a.z, b.z);
    v.w = packh2(a.w, b.w);
    *(uint4*)(g_whp + (size_t)flat * NHID + o4) = v;
}

// ---------------------------------------------------------------------------
// K2c: pack pf2 -> fp16 pair table: (f2pair, E2pair, E2apair, 0)
// ---------------------------------------------------------------------------
__global__ void k_p2h()
{
    int idx = blockIdx.x * blockDim.x + threadIdx.x;   // 0 .. GH*1536-1
    float4 a = g_pf2[(size_t)idx * 2];
    float4 b = g_pf2[(size_t)idx * 2 + 1];
    uint4 v;
    v.x = packh2(a.x, b.x);
    v.y = packh2(a.y, b.y);
    v.z = packh2(a.z, b.z);
    v.w = 0;
    g_f2h[idx] = v;
}

// ---------------------------------------------------------------------------
// K3: attention via fp16 mma, packed-half2 p-gen, S via ones-column mma.
// ---------------------------------------------------------------------------
__device__ __forceinline__ float eluf(float v) {
    return (v > 0.f) ? v : expm1f(v);
}
__device__ __forceinline__ u32 amask(u32 x) {   // 2 bits -> fp16x2 {0,1} mask
    return ((x & 1u) * 0x3C00u) | (((x >> 1) & 1u) * 0x3C000000u);
}
__device__ __forceinline__ u32 pgen(__half2 f1b, __half2 E1b, __half2 E1ab,
                                    u32 f2p, u32 E2p, u32 E2ap, u32 am) {
    __half2 t  = __hadd2(f1b, U2H(f2p));
    __half2 mg = __hgt2(t, U2H(0u));
    __half2 n1 = __hmul2(E1b,  U2H(E2p));
    __half2 n2 = __hmul2(E1ab, U2H(E2ap));
    __half2 pp = __hfma2(mg, __hsub2(n1, n2), n2);
    return H2U(__hmul2(pp, U2H(am)));
}

#define WP_STRIDE 72   // u32 per mpair row

__global__ void __launch_bounds__(256, 2) k_att_mma()
{
    __shared__ u32   WhP[32 * WP_STRIDE];   // 9216 B fp16x2 (m,m+1) per o
    __shared__ uint4 f2HS[32];              // per-mpair (f2p,E2p,E2ap)
    __shared__ float sS[128];

    const int tid = threadIdx.x, w = tid >> 5, l = tid & 31;
    const int bid  = blockIdx.x;
    const int tile = bid % 24;
    const int h    = (bid / 24) % NHEADS;
    const int g    = bid / (24 * NHEADS);
    const int gh   = g * NHEADS + h;
    const int nbase = tile * 128;

    const int rlo = w * 16 + (l >> 2);
    const int rhi = rlo + 8;

    // per-row fp16x2 broadcasts of (f1, E1, E1a)
    __half2 f1lo2, E1lo2, E1alo2, f1hi2, E1hi2, E1ahi2;
    {
        float4 p1lo = g_pf1[(size_t)gh * NN + nbase + rlo];
        float4 p1hi = g_pf1[(size_t)gh * NN + nbase + rhi];
        f1lo2  = __float2half2_rn(p1lo.x);
        E1lo2  = __float2half2_rn(p1lo.y);
        E1alo2 = __float2half2_rn(p1lo.z);
        f1hi2  = __float2half2_rn(p1hi.x);
        E1hi2  = __float2half2_rn(p1hi.y);
        E1ahi2 = __float2half2_rn(p1hi.z);
    }
    const u32 bone = ((l >> 2) == 0) ? 0x3C003C00u : 0u;   // ones column at n=0

    const u32* ab_lo = g_abits + ((size_t)g * NN + nbase + rlo) * (NN/32);
    const u32* ab_hi = g_abits + ((size_t)g * NN + nbase + rhi) * (NN/32);
    const u32* Whpg  = g_whp + (size_t)gh * (NN/2) * NHID;
    const uint4* f2g = g_f2h + (size_t)gh * (NN/2);

    float c[8][4];
    #pragma unroll
    for (int t = 0; t < 8; t++) { c[t][0]=0.f; c[t][1]=0.f; c[t][2]=0.f; c[t][3]=0.f; }
    float cS[4] = {0.f, 0.f, 0.f, 0.f};

    // staging geometry: thread covers mpair mp, o = og..og+7
    const int mp = tid >> 3;
    const int og = (tid & 7) * 8;

    uint4 w0pre, w1pre; uint4 fpre = make_uint4(0,0,0,0);
    u32 abl0, abl1, abh0, abh1;
    {
        const uint4* src = (const uint4*)(Whpg + (size_t)mp * NHID + og);
        w0pre = src[0]; w1pre = src[1];
        if (tid < 32) fpre = f2g[tid];
        abl0 = ab_lo[0]; abl1 = ab_lo[1];
        abh0 = ab_hi[0]; abh1 = ab_hi[1];
    }

    for (int i = 0; i < NN/64; i++) {
        __syncthreads();
        {
            uint4* d = (uint4*)&WhP[mp * WP_STRIDE + og];
            d[0] = w0pre; d[1] = w1pre;
            if (tid < 32) f2HS[tid] = fpre;
        }
        const u32 wl0 = abl0, wl1 = abl1, wh0 = abh0, wh1 = abh1;
        __syncthreads();

        if (i + 1 < NN/64) {
            const uint4* src = (const uint4*)(Whpg + (size_t)((i+1)*32 + mp) * NHID + og);
            w0pre = src[0]; w1pre = src[1];
            if (tid < 32) fpre = f2g[(i+1)*32 + tid];
            int wd = (i + 1) * 2;
            abl0 = ab_lo[wd]; abl1 = ab_lo[wd + 1];
            abh0 = ab_hi[wd]; abh1 = ab_hi[wd + 1];
        }

        #pragma unroll
        for (int kk = 0; kk < 4; kk++) {
            uint4 qa = f2HS[kk*8 + (l & 3)];        // mpairs m0,m0+1
            uint4 qb = f2HS[kk*8 + 4 + (l & 3)];    // mpairs m0+8,m0+9
            const u32 wlo = (kk < 2) ? wl0 : wl1;
            const u32 whi = (kk < 2) ? wh0 : wh1;
            const int bb = (kk & 1) * 16 + 2 * (l & 3);
            u32 a0 = pgen(f1lo2, E1lo2, E1alo2, qa.x, qa.y, qa.z, amask((wlo >> bb) & 3u));
            u32 a1 = pgen(f1hi2, E1hi2, E1ahi2, qa.x, qa.y, qa.z, amask((whi >> bb) & 3u));
            u32 a2 = pgen(f1lo2, E1lo2, E1alo2, qb.x, qb.y, qb.z, amask((wlo >> (bb+8)) & 3u));
            u32 a3 = pgen(f1hi2, E1hi2, E1ahi2, qb.x, qb.y, qb.z, amask((whi >> (bb+8)) & 3u));
            mma_f16(cS, a0, a1, a2, a3, bone, bone);   // row sums
            const u32* base0 = &WhP[(kk*8 + (l & 3)) * WP_STRIDE + (l >> 2)];
            #pragma unroll
            for (int t = 0; t < 8; t++) {
                u32 b0 = base0[8 * t];
                u32 b1 = base0[4 * WP_STRIDE + 8 * t];
                mma_f16(c[t], a0, a1, a2, a3, b0, b1);
            }
        }
    }

    // S sits in column 0: lanes with (l&3)==0, cS[0] = rlo, cS[2] = rhi
    if ((l & 3) == 0) { sS[rlo] = cS[0]; sS[rhi] = cS[2]; }
    __syncthreads();
    const float ilo = 1.0f / sS[rlo];
    const float ihi = 1.0f / sS[rhi];

    float* dlo = g_hcat + ((size_t)g * NN + nbase + rlo) * (NHEADS*NHID) + h * NHID;
    float* dhi = g_hcat + ((size_t)g * NN + nbase + rhi) * (NHEADS*NHID) + h * NHID;
    #pragma unroll
    for (int t = 0; t < 8; t++) {
        int col = 8 * t + 2 * (l & 3);
        float2 v;
        v.x = eluf(c[t][0] * ilo); v.y = eluf(c[t][1] * ilo);
        *(float2*)(dlo + col) = v;
        v.x = eluf(c[t][2] * ihi); v.y = eluf(c[t][3] * ihi);
        *(float2*)(dhi + col) = v;
    }
}

// ---------------------------------------------------------------------------
// K4: xi = elu(hcat . W_int + b)
// ---------------------------------------------------------------------------
__global__ void k_xi(const float* __restrict__ W_int, const float* __restrict__ b_int)
{
    __shared__ float Ws[NCLASS * 256];
    __shared__ float bs[NCLASS];
    const int tid = threadIdx.x, w = tid >> 5, lane = tid & 31;
    #pragma unroll
    for (int j = 0; j < 4; j++)
        *(float4*)&Ws[tid * 4 + j * 1024] = *(const float4*)(W_int + tid * 4 + j * 1024);
    if (tid < NCLASS) bs[tid] = b_int[tid];
    __syncthreads();

    long idx = (long)blockIdx.x * 8 + w;
    int g = (int)(idx / NN);
    int n = (int)(idx % NN);
    const float* hrow = g_hcat + ((size_t)g * NN + n) * 256;
    float v[8];
    #pragma unroll
    for (int j = 0; j < 8; j++) v[j] = hrow[lane + 32 * j];

    for (int c = 0; c < NCLASS; c++) {
        const float* wc = Ws + c * 256;
        float s = 0.f;
        #pragma unroll
        for (int j = 0; j < 8; j++) s += v[j] * wc[lane + 32 * j];
        #pragma unroll
        for (int o = 16; o >= 1; o >>= 1) s += __shfl_xor_sync(0xffffffffu, s, o);
        if (lane == 0) {
            float t = s + bs[c];
            t = (t > 0.f) ? t : expm1f(t);
            g_xib[(size_t)n * (NGRAPH*NCLASS) + g * NCLASS + c] = t;
        }
    }
}

// ---------------------------------------------------------------------------
// K5: out = log_softmax(xib @ W_fus^T + b_fus)
// ---------------------------------------------------------------------------
__global__ void k_out(const float* __restrict__ W_fus, const float* __restrict__ b_fus,
                      float* __restrict__ out)
{
    __shared__ float Wf[NCLASS * 48];
    __shared__ float bf[NCLASS];
    const int tid = threadIdx.x;
    for (int i = tid; i < NCLASS * 48; i += 256) Wf[i] = W_fus[i];
    if (tid < NCLASS) bf[tid] = b_fus[tid];
    __syncthreads();

    int n = blockIdx.x * 256 + tid;
    const float* xr = g_xib + (size_t)n * 48;
    float xv[48];
    #pragma unroll
    for (int j = 0; j < 48; j++) xv[j] = xr[j];

    float o[NCLASS];
    float mx = -FLT_MAX;
    #pragma unroll
    for (int c = 0; c < NCLASS; c++) {
        float s = bf[c];
        #pragma unroll
        for (int j = 0; j < 48; j++) s += xv[j] * Wf[c * 48 + j];
        o[c] = s;
        mx = fmaxf(mx, s);
    }
    float sum = 0.f;
    #pragma unroll
    for (int c = 0; c < NCLASS; c++) sum += expf(o[c] - mx);
    float lse = mx + logf(sum);
    float* dst = out + (size_t)n * NCLASS;
    #pragma unroll
    for (int c = 0; c < NCLASS; c++) dst[c] = o[c] - lse;
}

// ---------------------------------------------------------------------------
// K6: l1 = mean |W_fus|
// ---------------------------------------------------------------------------
__global__ void k_l1(const float* __restrict__ W_fus, float* __restrict__ out, int out_size)
{
    __shared__ float red[256];
    int tid = threadIdx.x;
    float s = 0.f;
    for (int i = tid; i < NCLASS * 48; i += 256) s += fabsf(W_fus[i]);
    red[tid] = s;
    __syncthreads();
    for (int o = 128; o >= 1; o >>= 1) {
        if (tid < o) red[tid] += red[tid + o];
        __syncthreads();
    }
    if (tid == 0) {
        float l1 = red[0] / (float)(NCLASS * 48);
        for (int i = NN * NCLASS; i < out_size; i++) out[i] = l1;
    }
}

extern "C" void kernel_launch(void* const* d_in, const int* in_sizes, int n_in,
                              void* d_out, int out_size)
{
    const float* x     = (const float*)d_in[0];
    const int*   adj   = (const int*)  d_in[1];
    const float* W     = (const float*)d_in[2];
    const float* a     = (const float*)d_in[3];
    const float* W_int = (const float*)d_in[4];
    const float* b_int = (const float*)d_in[5];
    const float* W_fus = (const float*)d_in[6];
    const float* b_fus = (const float*)d_in[7];
    float* out = (float*)d_out;

    k_cvt   <<<(XP_TOTAL + WP_TOTAL + 511) / 512, 512>>>(x, W);
    k_pack  <<<NGRAPH * NN / 8, 256>>>(adj);
    k_wh_mma<<<dim3(NN/128, GH), 256>>>();
    k_f12   <<<GH * NN / 8, 256>>>(a);
    k_whp   <<<GH * (NN/2) * (NHID/4) / 256, 256>>>();
    k_p2h   <<<GH * (NN/2) / 256, 256>>>();
    k_att_mma<<<NGRAPH * NHEADS * (NN/128), 256>>>();
    k_xi    <<<NGRAPH * NN / 8, 256>>>(W_int, b_int);
    k_out   <<<NN/256, 256>>>(W_fus, b_fus, out);
    k_l1    <<<1, 256>>>(W_fus, out, out_size);
}

// round 14
// speedup vs baseline: 5.4050x; 1.0918x over previous
#include <cuda_runtime.h>
#include <cuda_fp16.h>
#include <math.h>
#include <float.h>

#define NN 3072
#define FIN 512
#define NHID 64
#define NHEADS 4
#define NGRAPH 3
#define GH (NGRAPH*NHEADS)
#define NCLASS 16
#define ALPHA 0.2f

typedef unsigned long long u64;
typedef unsigned int u32;

// pack two floats into fp16x2 (lo = a, hi = b)
__device__ __forceinline__ u32 packh2(float a, float b) {
    u32 d; asm("cvt.rn.f16x2.f32 %0, %1, %2;" : "=r"(d) : "f"(b), "f"(a)); return d;
}
__device__ __forceinline__ __half2 U2H(u32 u) { return *reinterpret_cast<__half2*>(&u); }
__device__ __forceinline__ u32 H2U(__half2 h) { return *reinterpret_cast<u32*>(&h); }

// warp mma m16n8k16 fp16 (portable PTX since sm_80)
__device__ __forceinline__ void mma_f16(float* c, u32 a0, u32 a1, u32 a2, u32 a3,
                                        u32 b0, u32 b1) {
    asm volatile(
        "mma.sync.aligned.m16n8k16.row.col.f32.f16.f16.f32 "
        "{%0,%1,%2,%3}, {%4,%5,%6,%7}, {%8,%9}, {%0,%1,%2,%3};"
        : "+f"(c[0]), "+f"(c[1]), "+f"(c[2]), "+f"(c[3])
        : "r"(a0), "r"(a1), "r"(a2), "r"(a3), "r"(b0), "r"(b1));
}

// ---------------- device scratch ----------------
__device__ u32    g_xp [NN * (FIN/2)];           // x as fp16 (f,f+1) pairs [n][fp]
__device__ u32    g_wfp[GH * (FIN/2) * NHID];    // W as fp16 f-pairs [gh][fp][o]
__device__ u32    g_whp[GH * (NN/2) * NHID];     // Wh as fp16 (n,n+1) pairs [gh][np][o]
__device__ float4 g_pf1[GH * NN];                // (f1, exp(f1), exp(a*f1), 0)
__device__ uint4  g_f2h[GH * (NN/2)];            // fp16 pairs: (f2p, E2p, E2ap, 0)
__device__ u32    g_abits[NGRAPH * NN * (NN/32)];// [g][n][m/32]
__device__ float  g_hcat[NGRAPH * NN * (NHEADS*NHID)];
__device__ float  g_xib[NN * (NGRAPH*NCLASS)];

#define XP_TOTAL (NN * (FIN/2))                  // 786432
#define WP_TOTAL (GH * (FIN/2) * NHID)           // 196608

// ---------------------------------------------------------------------------
// K0: convert x and W to fp16 pair layouts
// ---------------------------------------------------------------------------
__global__ void k_cvt(const float* __restrict__ x, const float* __restrict__ W)
{
    int idx = blockIdx.x * blockDim.x + threadIdx.x;
    if (idx < XP_TOTAL) {
        int n = idx >> 8, fp = idx & 255;      // FIN/2 = 256
        const float* src = x + (size_t)n * FIN + 2 * fp;
        g_xp[idx] = packh2(src[0], src[1]);
    } else {
        int j = idx - XP_TOTAL;
        if (j < WP_TOTAL) {
            int gh = j / ((FIN/2) * NHID);
            int r  = j % ((FIN/2) * NHID);
            int fp = r >> 6, o = r & 63;
            const float* src = W + ((size_t)gh * FIN + 2 * fp) * NHID + o;
            g_wfp[j] = packh2(src[0], src[NHID]);
        }
    }
}

// ---------------------------------------------------------------------------
// K1b: pack adjacency into bitmask — int4 loads + shfl-or word assembly
// ---------------------------------------------------------------------------
__global__ void k_pack(const int* __restrict__ adj)
{
    int w = threadIdx.x >> 5, l = threadIdx.x & 31;
    long row = (long)blockIdx.x * 8 + w;          // 0 .. NGRAPH*NN-1
    const int4* ar = (const int4*)(adj + (size_t)row * NN);
    u32* dst = g_abits + (size_t)row * (NN/32);
    #pragma unroll 4
    for (int j = 0; j < NN/128; j++) {            // 24 iters, 16B/lane
        int4 v = ar[j * 32 + l];
        u32 nib = (u32)(v.x > 0) | ((u32)(v.y > 0) << 1)
                | ((u32)(v.z > 0) << 2) | ((u32)(v.w > 0) << 3);
        u32 word = nib << (4 * (l & 7));
        word |= __shfl_xor_sync(0xffffffffu, word, 1);
        word |= __shfl_xor_sync(0xffffffffu, word, 2);
        word |= __shfl_xor_sync(0xffffffffu, word, 4);
        if ((l & 7) == 0) dst[j * 4 + (l >> 3)] = word;
    }
}

// ---------------------------------------------------------------------------
// K1: Wh = x @ W via fp16 mma, FUSED epilogue:
//   - f1/f2 dots (quad-shuffle reduce over the fp32 accumulators)
//   - exp tables: g_pf1 (fp32), g_f2h (fp16 row-pairs)
//   - g_whp fp16 (n,n+1)-pair Wh (row pairing via shfl_down 4)
// No fp32 Wh ever hits gmem.
// ---------------------------------------------------------------------------
#define AX_STRIDE 36   // u32 per n-row (32 fpairs + pad)
#define WF_STRIDE 72   // u32 per fpair-row (64 o + pad)

__global__ void __launch_bounds__(256, 2) k_wh_mma(const float* __restrict__ a)
{
    __shared__ u32 AxS[128 * AX_STRIDE];   // 18.4 KB
    __shared__ u32 WfS[32 * WF_STRIDE];    // 9.2 KB
    __shared__ float aS[2 * NHID];         // a1 | a2 for this gh

    const int tid = threadIdx.x, w = tid >> 5, l = tid & 31;
    const int nbase = blockIdx.x * 128;
    const int gh = blockIdx.y;
    const int rlo = w * 16 + (l >> 2);
    const int rhi = rlo + 8;
    const int q = l & 3;

    if (tid < 128) aS[tid] = a[(size_t)gh * 2 * NHID + tid];

    float c[8][4];
    #pragma unroll
    for (int t = 0; t < 8; t++) { c[t][0]=0.f; c[t][1]=0.f; c[t][2]=0.f; c[t][3]=0.f; }

    // staging geometry
    const int an  = tid >> 1;                 // A: n row 0..127
    const int afp = (tid & 1) * 16;           // A: fp base 0/16
    const int bfp = tid >> 3;                 // B: fpair row 0..31
    const int bog = (tid & 7) * 8;            // B: o base

    uint4 apre[4]; uint4 bpre[2];
    {
        const uint4* as = (const uint4*)(g_xp + (size_t)(nbase + an) * (FIN/2) + afp);
        #pragma unroll
        for (int j = 0; j < 4; j++) apre[j] = as[j];
        const uint4* bs = (const uint4*)(g_wfp + ((size_t)gh * (FIN/2) + bfp) * NHID + bog);
        bpre[0] = bs[0]; bpre[1] = bs[1];
    }

    for (int ch = 0; ch < FIN/64; ch++) {
        __syncthreads();
        {
            uint4* ad = (uint4*)&AxS[an * AX_STRIDE + afp];
            #pragma unroll
            for (int j = 0; j < 4; j++) ad[j] = apre[j];
            uint4* bd = (uint4*)&WfS[bfp * WF_STRIDE + bog];
            bd[0] = bpre[0]; bd[1] = bpre[1];
        }
        __syncthreads();
        if (ch + 1 < FIN/64) {
            const uint4* as = (const uint4*)(g_xp + (size_t)(nbase + an) * (FIN/2) + (ch+1)*32 + afp);
            #pragma unroll
            for (int j = 0; j < 4; j++) apre[j] = as[j];
            const uint4* bs = (const uint4*)(g_wfp + ((size_t)gh * (FIN/2) + (ch+1)*32 + bfp) * NHID + bog);
            bpre[0] = bs[0]; bpre[1] = bs[1];
        }
        #pragma unroll
        for (int kk = 0; kk < 4; kk++) {
            u32 a0 = AxS[rlo * AX_STRIDE + kk*8 + q];
            u32 a1 = AxS[rhi * AX_STRIDE + kk*8 + q];
            u32 a2 = AxS[rlo * AX_STRIDE + kk*8 + 4 + q];
            u32 a3 = AxS[rhi * AX_STRIDE + kk*8 + 4 + q];
            const u32* bb0 = &WfS[(kk*8 + q) * WF_STRIDE + (l >> 2)];
            #pragma unroll
            for (int t = 0; t < 8; t++) {
                u32 b0 = bb0[8 * t];
                u32 b1 = bb0[4 * WF_STRIDE + 8 * t];
                mma_f16(c[t], a0, a1, a2, a3, b0, b1);
            }
        }
    }

    // ---- fused epilogue ----
    const int nlo = nbase + rlo, nhi = nbase + rhi;

    // f1/f2 dots over this thread's 16 columns per row, then quad reduce
    float f1lo = 0.f, f2lo = 0.f, f1hi = 0.f, f2hi = 0.f;
    #pragma unroll
    for (int t = 0; t < 8; t++) {
        int o0 = 8*t + 2*q;
        float2 a1v = *(const float2*)&aS[o0];
        float2 a2v = *(const float2*)&aS[NHID + o0];
        f1lo += c[t][0]*a1v.x + c[t][1]*a1v.y;
        f2lo += c[t][0]*a2v.x + c[t][1]*a2v.y;
        f1hi += c[t][2]*a1v.x + c[t][3]*a1v.y;
        f2hi += c[t][2]*a2v.x + c[t][3]*a2v.y;
    }
    #pragma unroll
    for (int o = 1; o <= 2; o <<= 1) {
        f1lo += __shfl_xor_sync(0xffffffffu, f1lo, o);
        f2lo += __shfl_xor_sync(0xffffffffu, f2lo, o);
        f1hi += __shfl_xor_sync(0xffffffffu, f1hi, o);
        f2hi += __shfl_xor_sync(0xffffffffu, f2hi, o);
    }

    if (q == 0) {
        float4 v;
        v.x = f1lo; v.y = __expf(f1lo); v.z = __expf(ALPHA * f1lo); v.w = 0.f;
        g_pf1[(size_t)gh * NN + nlo] = v;
        v.x = f1hi; v.y = __expf(f1hi); v.z = __expf(ALPHA * f1hi); v.w = 0.f;
        g_pf1[(size_t)gh * NN + nhi] = v;
    }

    // row-pair (n, n+1): lane l pairs with lane l+4 ((l>>2)+1)
    const bool evenr = (((l >> 2) & 1) == 0);
    float f2lon = __shfl_down_sync(0xffffffffu, f2lo, 4);
    float f2hin = __shfl_down_sync(0xffffffffu, f2hi, 4);
    if (q == 0 && evenr) {
        uint4 v;
        v.x = packh2(f2lo, f2lon);
        v.y = packh2(__expf(f2lo), __expf(f2lon));
        v.z = packh2(__expf(ALPHA * f2lo), __expf(ALPHA * f2lon));
        v.w = 0;
        g_f2h[(size_t)gh * (NN/2) + (nlo >> 1)] = v;
        v.x = packh2(f2hi, f2hin);
        v.y = packh2(__expf(f2hi), __expf(f2hin));
        v.z = packh2(__expf(ALPHA * f2hi), __expf(ALPHA * f2hin));
        v.w = 0;
        g_f2h[(size_t)gh * (NN/2) + (nhi >> 1)] = v;
    }

    // whp: fp16 (n,n+1) pairs
    u32* wlo_base = g_whp + ((size_t)gh * (NN/2) + (nlo >> 1)) * NHID;
    u32* whi_base = g_whp + ((size_t)gh * (NN/2) + (nhi >> 1)) * NHID;
    #pragma unroll
    for (int t = 0; t < 8; t++) {
        float n0 = __shfl_down_sync(0xffffffffu, c[t][0], 4);
        float n1 = __shfl_down_sync(0xffffffffu, c[t][1], 4);
        float n2 = __shfl_down_sync(0xffffffffu, c[t][2], 4);
        float n3 = __shfl_down_sync(0xffffffffu, c[t][3], 4);
        if (evenr) {
            int col = 8*t + 2*q;
            uint2 v;
            v.x = packh2(c[t][0], n0);
            v.y = packh2(c[t][1], n1);
            *(uint2*)(wlo_base + col) = v;
            v.x = packh2(c[t][2], n2);
            v.y = packh2(c[t][3], n3);
            *(uint2*)(whi_base + col) = v;
        }
    }
}

// ---------------------------------------------------------------------------
// K3: attention via fp16 mma, packed-half2 p-gen, S via ones-column mma.
// (unchanged from round-10 passing kernel)
// ---------------------------------------------------------------------------
__device__ __forceinline__ float eluf(float v) {
    return (v > 0.f) ? v : expm1f(v);
}
__device__ __forceinline__ u32 amask(u32 x) {   // 2 bits -> fp16x2 {0,1} mask
    return ((x & 1u) * 0x3C00u) | (((x >> 1) & 1u) * 0x3C000000u);
}
__device__ __forceinline__ u32 pgen(__half2 f1b, __half2 E1b, __half2 E1ab,
                                    u32 f2p, u32 E2p, u32 E2ap, u32 am) {
    __half2 t  = __hadd2(f1b, U2H(f2p));
    __half2 mg = __hgt2(t, U2H(0u));
    __half2 n1 = __hmul2(E1b,  U2H(E2p));
    __half2 n2 = __hmul2(E1ab, U2H(E2ap));
    __half2 pp = __hfma2(mg, __hsub2(n1, n2), n2);
    return H2U(__hmul2(pp, U2H(am)));
}

#define WP_STRIDE 72   // u32 per mpair row

__global__ void __launch_bounds__(256, 2) k_att_mma()
{
    __shared__ u32   WhP[32 * WP_STRIDE];   // 9216 B fp16x2 (m,m+1) per o
    __shared__ uint4 f2HS[32];              // per-mpair (f2p,E2p,E2ap)
    __shared__ float sS[128];

    const int tid = threadIdx.x, w = tid >> 5, l = tid & 31;
    const int bid  = blockIdx.x;
    const int tile = bid % 24;
    const int h    = (bid / 24) % NHEADS;
    const int g    = bid / (24 * NHEADS);
    const int gh   = g * NHEADS + h;
    const int nbase = tile * 128;

    const int rlo = w * 16 + (l >> 2);
    const int rhi = rlo + 8;

    // per-row fp16x2 broadcasts of (f1, E1, E1a)
    __half2 f1lo2, E1lo2, E1alo2, f1hi2, E1hi2, E1ahi2;
    {
        float4 p1lo = g_pf1[(size_t)gh * NN + nbase + rlo];
        float4 p1hi = g_pf1[(size_t)gh * NN + nbase + rhi];
        f1lo2  = __float2half2_rn(p1lo.x);
        E1lo2  = __float2half2_rn(p1lo.y);
        E1alo2 = __float2half2_rn(p1lo.z);
        f1hi2  = __float2half2_rn(p1hi.x);
        E1hi2  = __float2half2_rn(p1hi.y);
        E1ahi2 = __float2half2_rn(p1hi.z);
    }
    const u32 bone = ((l >> 2) == 0) ? 0x3C003C00u : 0u;   // ones column at n=0

    const u32* ab_lo = g_abits + ((size_t)g * NN + nbase + rlo) * (NN/32);
    const u32* ab_hi = g_abits + ((size_t)g * NN + nbase + rhi) * (NN/32);
    const u32* Whpg  = g_whp + (size_t)gh * (NN/2) * NHID;
    const uint4* f2g = g_f2h + (size_t)gh * (NN/2);

    float c[8][4];
    #pragma unroll
    for (int t = 0; t < 8; t++) { c[t][0]=0.f; c[t][1]=0.f; c[t][2]=0.f; c[t][3]=0.f; }
    float cS[4] = {0.f, 0.f, 0.f, 0.f};

    // staging geometry: thread covers mpair mp, o = og..og+7
    const int mp = tid >> 3;
    const int og = (tid & 7) * 8;

    uint4 w0pre, w1pre; uint4 fpre = make_uint4(0,0,0,0);
    u32 abl0, abl1, abh0, abh1;
    {
        const uint4* src = (const uint4*)(Whpg + (size_t)mp * NHID + og);
        w0pre = src[0]; w1pre = src[1];
        if (tid < 32) fpre = f2g[tid];
        abl0 = ab_lo[0]; abl1 = ab_lo[1];
        abh0 = ab_hi[0]; abh1 = ab_hi[1];
    }

    for (int i = 0; i < NN/64; i++) {
        __syncthreads();
        {
            uint4* d = (uint4*)&WhP[mp * WP_STRIDE + og];
            d[0] = w0pre; d[1] = w1pre;
            if (tid < 32) f2HS[tid] = fpre;
        }
        const u32 wl0 = abl0, wl1 = abl1, wh0 = abh0, wh1 = abh1;
        __syncthreads();

        if (i + 1 < NN/64) {
            const uint4* src = (const uint4*)(Whpg + (size_t)((i+1)*32 + mp) * NHID + og);
            w0pre = src[0]; w1pre = src[1];
            if (tid < 32) fpre = f2g[(i+1)*32 + tid];
            int wd = (i + 1) * 2;
            abl0 = ab_lo[wd]; abl1 = ab_lo[wd + 1];
            abh0 = ab_hi[wd]; abh1 = ab_hi[wd + 1];
        }

        #pragma unroll
        for (int kk = 0; kk < 4; kk++) {
            uint4 qa = f2HS[kk*8 + (l & 3)];        // mpairs m0,m0+1
            uint4 qb = f2HS[kk*8 + 4 + (l & 3)];    // mpairs m0+8,m0+9
            const u32 wlo = (kk < 2) ? wl0 : wl1;
            const u32 whi = (kk < 2) ? wh0 : wh1;
            const int bb = (kk & 1) * 16 + 2 * (l & 3);
            u32 a0 = pgen(f1lo2, E1lo2, E1alo2, qa.x, qa.y, qa.z, amask((wlo >> bb) & 3u));
            u32 a1 = pgen(f1hi2, E1hi2, E1ahi2, qa.x, qa.y, qa.z, amask((whi >> bb) & 3u));
            u32 a2 = pgen(f1lo2, E1lo2, E1alo2, qb.x, qb.y, qb.z, amask((wlo >> (bb+8)) & 3u));
            u32 a3 = pgen(f1hi2, E1hi2, E1ahi2, qb.x, qb.y, qb.z, amask((whi >> (bb+8)) & 3u));
            mma_f16(cS, a0, a1, a2, a3, bone, bone);   // row sums
            const u32* base0 = &WhP[(kk*8 + (l & 3)) * WP_STRIDE + (l >> 2)];
            #pragma unroll
            for (int t = 0; t < 8; t++) {
                u32 b0 = base0[8 * t];
                u32 b1 = base0[4 * WP_STRIDE + 8 * t];
                mma_f16(c[t], a0, a1, a2, a3, b0, b1);
            }
        }
    }

    // S sits in column 0: lanes with (l&3)==0, cS[0] = rlo, cS[2] = rhi
    if ((l & 3) == 0) { sS[rlo] = cS[0]; sS[rhi] = cS[2]; }
    __syncthreads();
    const float ilo = 1.0f / sS[rlo];
    const float ihi = 1.0f / sS[rhi];

    float* dlo = g_hcat + ((size_t)g * NN + nbase + rlo) * (NHEADS*NHID) + h * NHID;
    float* dhi = g_hcat + ((size_t)g * NN + nbase + rhi) * (NHEADS*NHID) + h * NHID;
    #pragma unroll
    for (int t = 0; t < 8; t++) {
        int col = 8 * t + 2 * (l & 3);
        float2 v;
        v.x = eluf(c[t][0] * ilo); v.y = eluf(c[t][1] * ilo);
        *(float2*)(dlo + col) = v;
        v.x = eluf(c[t][2] * ihi); v.y = eluf(c[t][3] * ihi);
        *(float2*)(dhi + col) = v;
    }
}

// ---------------------------------------------------------------------------
// K4: xi = elu(hcat . W_int + b)
// ---------------------------------------------------------------------------
__global__ void k_xi(const float* __restrict__ W_int, const float* __restrict__ b_int)
{
    __shared__ float Ws[NCLASS * 256];
    __shared__ float bs[NCLASS];
    const int tid = threadIdx.x, w = tid >> 5, lane = tid & 31;
    #pragma unroll
    for (int j = 0; j < 4; j++)
        *(float4*)&Ws[tid * 4 + j * 1024] = *(const float4*)(W_int + tid * 4 + j * 1024);
    if (tid < NCLASS) bs[tid] = b_int[tid];
    __syncthreads();

    long idx = (long)blockIdx.x * 8 + w;
    int g = (int)(idx / NN);
    int n = (int)(idx % NN);
    const float* hrow = g_hcat + ((size_t)g * NN + n) * 256;
    float v[8];
    #pragma unroll
    for (int j = 0; j < 8; j++) v[j] = hrow[lane + 32 * j];

    for (int c = 0; c < NCLASS; c++) {
        const float* wc = Ws + c * 256;
        float s = 0.f;
        #pragma unroll
        for (int j = 0; j < 8; j++) s += v[j] * wc[lane + 32 * j];
        #pragma unroll
        for (int o = 16; o >= 1; o >>= 1) s += __shfl_xor_sync(0xffffffffu, s, o);
        if (lane == 0) {
            float t = s + bs[c];
            t = (t > 0.f) ? t : expm1f(t);
            g_xib[(size_t)n * (NGRAPH*NCLASS) + g * NCLASS + c] = t;
        }
    }
}

// ---------------------------------------------------------------------------
// K5: out = log_softmax(xib @ W_fus^T + b_fus)
// ---------------------------------------------------------------------------
__global__ void k_out(const float* __restrict__ W_fus, const float* __restrict__ b_fus,
                      float* __restrict__ out)
{
    __shared__ float Wf[NCLASS * 48];
    __shared__ float bf[NCLASS];
    const int tid = threadIdx.x;
    for (int i = tid; i < NCLASS * 48; i += 256) Wf[i] = W_fus[i];
    if (tid < NCLASS) bf[tid] = b_fus[tid];
    __syncthreads();

    int n = blockIdx.x * 256 + tid;
    const float* xr = g_xib + (size_t)n * 48;
    float xv[48];
    #pragma unroll
    for (int j = 0; j < 48; j++) xv[j] = xr[j];

    float o[NCLASS];
    float mx = -FLT_MAX;
    #pragma unroll
    for (int c = 0; c < NCLASS; c++) {
        float s = bf[c];
        #pragma unroll
        for (int j = 0; j < 48; j++) s += xv[j] * Wf[c * 48 + j];
        o[c] = s;
        mx = fmaxf(mx, s);
    }
    float sum = 0.f;
    #pragma unroll
    for (int c = 0; c < NCLASS; c++) sum += expf(o[c] - mx);
    float lse = mx + logf(sum);
    float* dst = out + (size_t)n * NCLASS;
    #pragma unroll
    for (int c = 0; c < NCLASS; c++) dst[c] = o[c] - lse;
}

// ---------------------------------------------------------------------------
// K6: l1 = mean |W_fus|
// ---------------------------------------------------------------------------
__global__ void k_l1(const float* __restrict__ W_fus, float* __restrict__ out, int out_size)
{
    __shared__ float red[256];
    int tid = threadIdx.x;
    float s = 0.f;
    for (int i = tid; i < NCLASS * 48; i += 256) s += fabsf(W_fus[i]);
    red[tid] = s;
    __syncthreads();
    for (int o = 128; o >= 1; o >>= 1) {
        if (tid < o) red[tid] += red[tid + o];
        __syncthreads();
    }
    if (tid == 0) {
        float l1 = red[0] / (float)(NCLASS * 48);
        for (int i = NN * NCLASS; i < out_size; i++) out[i] = l1;
    }
}

extern "C" void kernel_launch(void* const* d_in, const int* in_sizes, int n_in,
                              void* d_out, int out_size)
{
    const float* x     = (const float*)d_in[0];
    const int*   adj   = (const int*)  d_in[1];
    const float* W     = (const float*)d_in[2];
    const float* a     = (const float*)d_in[3];
    const float* W_int = (const float*)d_in[4];
    const float* b_int = (const float*)d_in[5];
    const float* W_fus = (const float*)d_in[6];
    const float* b_fus = (const float*)d_in[7];
    float* out = (float*)d_out;

    k_cvt   <<<(XP_TOTAL + WP_TOTAL + 511) / 512, 512>>>(x, W);
    k_pack  <<<NGRAPH * NN / 8, 256>>>(adj);
    k_wh_mma<<<dim3(NN/128, GH), 256>>>(a);
    k_att_mma<<<NGRAPH * NHEADS * (NN/128), 256>>>();
    k_xi    <<<NGRAPH * NN / 8, 256>>>(W_int, b_int);
    k_out   <<<NN/256, 256>>>(W_fus, b_fus, out);
    k_l1    <<<1, 256>>>(W_fus, out, out_size);
}

// round 16
// speedup vs baseline: 5.4776x; 1.0134x over previous
#include <cuda_runtime.h>
#include <cuda_fp16.h>
#include <math.h>
#include <float.h>

#define NN 3072
#define FIN 512
#define NHID 64
#define NHEADS 4
#define NGRAPH 3
#define GH (NGRAPH*NHEADS)
#define NCLASS 16
#define ALPHA 0.2f

typedef unsigned long long u64;
typedef unsigned int u32;

// pack two floats into fp16x2 (lo = a, hi = b)
__device__ __forceinline__ u32 packh2(float a, float b) {
    u32 d; asm("cvt.rn.f16x2.f32 %0, %1, %2;" : "=r"(d) : "f"(b), "f"(a)); return d;
}
__device__ __forceinline__ __half2 U2H(u32 u) { return *reinterpret_cast<__half2*>(&u); }
__device__ __forceinline__ u32 H2U(__half2 h) { return *reinterpret_cast<u32*>(&h); }

// warp mma m16n8k16 fp16 (portable PTX since sm_80)
__device__ __forceinline__ void mma_f16(float* c, u32 a0, u32 a1, u32 a2, u32 a3,
                                        u32 b0, u32 b1) {
    asm volatile(
        "mma.sync.aligned.m16n8k16.row.col.f32.f16.f16.f32 "
        "{%0,%1,%2,%3}, {%4,%5,%6,%7}, {%8,%9}, {%0,%1,%2,%3};"
        : "+f"(c[0]), "+f"(c[1]), "+f"(c[2]), "+f"(c[3])
        : "r"(a0), "r"(a1), "r"(a2), "r"(a3), "r"(b0), "r"(b1));
}

// ---------------- device scratch ----------------
__device__ u32    g_xp [NN * (FIN/2)];           // x as fp16 (f,f+1) pairs [n][fp]
__device__ u32    g_wfp[GH * (FIN/2) * NHID];    // W as fp16 f-pairs [gh][fp][o]
__device__ u32    g_whp[GH * (NN/2) * NHID];     // Wh as fp16 (n,n+1) pairs [gh][np][o]
__device__ float4 g_pf1[GH * NN];                // (f1, exp(f1), exp(a*f1), 0)
__device__ uint4  g_f2h[GH * (NN/2)];            // fp16 pairs: (f2p, E2p, E2ap, 0)
__device__ u32    g_abits[NGRAPH * NN * (NN/32)];// [g][n][m/32]
__device__ float  g_hcat[NGRAPH * NN * (NHEADS*NHID)];
__device__ float  g_xib[NN * (NGRAPH*NCLASS)];

#define XP_TOTAL (NN * (FIN/2))                  // 786432
#define WP_TOTAL (GH * (FIN/2) * NHID)           // 196608

// ---------------------------------------------------------------------------
// K0: convert x and W to fp16 pair layouts
// ---------------------------------------------------------------------------
__global__ void k_cvt(const float* __restrict__ x, const float* __restrict__ W)
{
    int idx = blockIdx.x * blockDim.x + threadIdx.x;
    if (idx < XP_TOTAL) {
        int n = idx >> 8, fp = idx & 255;      // FIN/2 = 256
        const float* src = x + (size_t)n * FIN + 2 * fp;
        g_xp[idx] = packh2(src[0], src[1]);
    } else {
        int j = idx - XP_TOTAL;
        if (j < WP_TOTAL) {
            int gh = j / ((FIN/2) * NHID);
            int r  = j % ((FIN/2) * NHID);
            int fp = r >> 6, o = r & 63;
            const float* src = W + ((size_t)gh * FIN + 2 * fp) * NHID + o;
            g_wfp[j] = packh2(src[0], src[NHID]);
        }
    }
}

// ---------------------------------------------------------------------------
// K1b: pack adjacency into bitmask — int4 loads + shfl-or word assembly
// ---------------------------------------------------------------------------
__global__ void k_pack(const int* __restrict__ adj)
{
    int w = threadIdx.x >> 5, l = threadIdx.x & 31;
    long row = (long)blockIdx.x * 8 + w;          // 0 .. NGRAPH*NN-1
    const int4* ar = (const int4*)(adj + (size_t)row * NN);
    u32* dst = g_abits + (size_t)row * (NN/32);
    #pragma unroll 4
    for (int j = 0; j < NN/128; j++) {            // 24 iters, 16B/lane
        int4 v = ar[j * 32 + l];
        u32 nib = (u32)(v.x > 0) | ((u32)(v.y > 0) << 1)
                | ((u32)(v.z > 0) << 2) | ((u32)(v.w > 0) << 3);
        u32 word = nib << (4 * (l & 7));
        word |= __shfl_xor_sync(0xffffffffu, word, 1);
        word |= __shfl_xor_sync(0xffffffffu, word, 2);
        word |= __shfl_xor_sync(0xffffffffu, word, 4);
        if ((l & 7) == 0) dst[j * 4 + (l >> 3)] = word;
    }
}

// ---------------------------------------------------------------------------
// K1: Wh = x @ W via fp16 mma, FUSED epilogue (f1/f2, exp tables, fp16 Wh pairs)
// ---------------------------------------------------------------------------
#define AX_STRIDE 36   // u32 per n-row (32 fpairs + pad)
#define WF_STRIDE 72   // u32 per fpair-row (64 o + pad)

__global__ void __launch_bounds__(256, 2) k_wh_mma(const float* __restrict__ a)
{
    __shared__ u32 AxS[128 * AX_STRIDE];   // 18.4 KB
    __shared__ u32 WfS[32 * WF_STRIDE];    // 9.2 KB
    __shared__ float aS[2 * NHID];         // a1 | a2 for this gh

    const int tid = threadIdx.x, w = tid >> 5, l = tid & 31;
    const int nbase = blockIdx.x * 128;
    const int gh = blockIdx.y;
    const int rlo = w * 16 + (l >> 2);
    const int rhi = rlo + 8;
    const int q = l & 3;

    if (tid < 128) aS[tid] = a[(size_t)gh * 2 * NHID + tid];

    float c[8][4];
    #pragma unroll
    for (int t = 0; t < 8; t++) { c[t][0]=0.f; c[t][1]=0.f; c[t][2]=0.f; c[t][3]=0.f; }

    // staging geometry
    const int an  = tid >> 1;                 // A: n row 0..127
    const int afp = (tid & 1) * 16;           // A: fp base 0/16
    const int bfp = tid >> 3;                 // B: fpair row 0..31
    const int bog = (tid & 7) * 8;            // B: o base

    uint4 apre[4]; uint4 bpre[2];
    {
        const uint4* as = (const uint4*)(g_xp + (size_t)(nbase + an) * (FIN/2) + afp);
        #pragma unroll
        for (int j = 0; j < 4; j++) apre[j] = as[j];
        const uint4* bs = (const uint4*)(g_wfp + ((size_t)gh * (FIN/2) + bfp) * NHID + bog);
        bpre[0] = bs[0]; bpre[1] = bs[1];
    }

    for (int ch = 0; ch < FIN/64; ch++) {
        __syncthreads();
        {
            uint4* ad = (uint4*)&AxS[an * AX_STRIDE + afp];
            #pragma unroll
            for (int j = 0; j < 4; j++) ad[j] = apre[j];
            uint4* bd = (uint4*)&WfS[bfp * WF_STRIDE + bog];
            bd[0] = bpre[0]; bd[1] = bpre[1];
        }
        __syncthreads();
        if (ch + 1 < FIN/64) {
            const uint4* as = (const uint4*)(g_xp + (size_t)(nbase + an) * (FIN/2) + (ch+1)*32 + afp);
            #pragma unroll
            for (int j = 0; j < 4; j++) apre[j] = as[j];
            const uint4* bs = (const uint4*)(g_wfp + ((size_t)gh * (FIN/2) + (ch+1)*32 + bfp) * NHID + bog);
            bpre[0] = bs[0]; bpre[1] = bs[1];
        }
        #pragma unroll
        for (int kk = 0; kk < 4; kk++) {
            u32 a0 = AxS[rlo * AX_STRIDE + kk*8 + q];
            u32 a1 = AxS[rhi * AX_STRIDE + kk*8 + q];
            u32 a2 = AxS[rlo * AX_STRIDE + kk*8 + 4 + q];
            u32 a3 = AxS[rhi * AX_STRIDE + kk*8 + 4 + q];
            const u32* bb0 = &WfS[(kk*8 + q) * WF_STRIDE + (l >> 2)];
            #pragma unroll
            for (int t = 0; t < 8; t++) {
                u32 b0 = bb0[8 * t];
                u32 b1 = bb0[4 * WF_STRIDE + 8 * t];
                mma_f16(c[t], a0, a1, a2, a3, b0, b1);
            }
        }
    }

    // ---- fused epilogue ----
    const int nlo = nbase + rlo, nhi = nbase + rhi;

    float f1lo = 0.f, f2lo = 0.f, f1hi = 0.f, f2hi = 0.f;
    #pragma unroll
    for (int t = 0; t < 8; t++) {
        int o0 = 8*t + 2*q;
        float2 a1v = *(const float2*)&aS[o0];
        float2 a2v = *(const float2*)&aS[NHID + o0];
        f1lo += c[t][0]*a1v.x + c[t][1]*a1v.y;
        f2lo += c[t][0]*a2v.x + c[t][1]*a2v.y;
        f1hi += c[t][2]*a1v.x + c[t][3]*a1v.y;
        f2hi += c[t][2]*a2v.x + c[t][3]*a2v.y;
    }
    #pragma unroll
    for (int o = 1; o <= 2; o <<= 1) {
        f1lo += __shfl_xor_sync(0xffffffffu, f1lo, o);
        f2lo += __shfl_xor_sync(0xffffffffu, f2lo, o);
        f1hi += __shfl_xor_sync(0xffffffffu, f1hi, o);
        f2hi += __shfl_xor_sync(0xffffffffu, f2hi, o);
    }

    if (q == 0) {
        float4 v;
        v.x = f1lo; v.y = __expf(f1lo); v.z = __expf(ALPHA * f1lo); v.w = 0.f;
        g_pf1[(size_t)gh * NN + nlo] = v;
        v.x = f1hi; v.y = __expf(f1hi); v.z = __expf(ALPHA * f1hi); v.w = 0.f;
        g_pf1[(size_t)gh * NN + nhi] = v;
    }

    const bool evenr = (((l >> 2) & 1) == 0);
    float f2lon = __shfl_down_sync(0xffffffffu, f2lo, 4);
    float f2hin = __shfl_down_sync(0xffffffffu, f2hi, 4);
    if (q == 0 && evenr) {
        uint4 v;
        v.x = packh2(f2lo, f2lon);
        v.y = packh2(__expf(f2lo), __expf(f2lon));
        v.z = packh2(__expf(ALPHA * f2lo), __expf(ALPHA * f2lon));
        v.w = 0;
        g_f2h[(size_t)gh * (NN/2) + (nlo >> 1)] = v;
        v.x = packh2(f2hi, f2hin);
        v.y = packh2(__expf(f2hi), __expf(f2hin));
        v.z = packh2(__expf(ALPHA * f2hi), __expf(ALPHA * f2hin));
        v.w = 0;
        g_f2h[(size_t)gh * (NN/2) + (nhi >> 1)] = v;
    }

    u32* wlo_base = g_whp + ((size_t)gh * (NN/2) + (nlo >> 1)) * NHID;
    u32* whi_base = g_whp + ((size_t)gh * (NN/2) + (nhi >> 1)) * NHID;
    #pragma unroll
    for (int t = 0; t < 8; t++) {
        float n0 = __shfl_down_sync(0xffffffffu, c[t][0], 4);
        float n1 = __shfl_down_sync(0xffffffffu, c[t][1], 4);
        float n2 = __shfl_down_sync(0xffffffffu, c[t][2], 4);
        float n3 = __shfl_down_sync(0xffffffffu, c[t][3], 4);
        if (evenr) {
            int col = 8*t + 2*q;
            uint2 v;
            v.x = packh2(c[t][0], n0);
            v.y = packh2(c[t][1], n1);
            *(uint2*)(wlo_base + col) = v;
            v.x = packh2(c[t][2], n2);
            v.y = packh2(c[t][3], n3);
            *(uint2*)(whi_base + col) = v;
        }
    }
}

// ---------------------------------------------------------------------------
// K3: attention. 128 threads = 4 warps, 32 rows/warp (two stacked m16 tiles
// sharing each B-fragment) -> B-frag crossbar bytes per output row halved.
// ---------------------------------------------------------------------------
__device__ __forceinline__ float eluf(float v) {
    return (v > 0.f) ? v : expm1f(v);
}
__device__ __forceinline__ u32 amask(u32 x) {   // 2 bits -> fp16x2 {0,1} mask
    return ((x & 1u) * 0x3C00u) | (((x >> 1) & 1u) * 0x3C000000u);
}
__device__ __forceinline__ u32 pgen(__half2 f1b, __half2 E1b, __half2 E1ab,
                                    u32 f2p, u32 E2p, u32 E2ap, u32 am) {
    __half2 t  = __hadd2(f1b, U2H(f2p));
    __half2 mg = __hgt2(t, U2H(0u));
    __half2 n1 = __hmul2(E1b,  U2H(E2p));
    __half2 n2 = __hmul2(E1ab, U2H(E2ap));
    __half2 pp = __hfma2(mg, __hsub2(n1, n2), n2);
    return H2U(__hmul2(pp, U2H(am)));
}

#define WP_STRIDE 72   // u32 per mpair row

__global__ void __launch_bounds__(128, 3) k_att_mma()
{
    __shared__ u32   WhP[32 * WP_STRIDE];   // 9216 B fp16x2 (m,m+1) per o
    __shared__ uint4 f2HS[32];              // per-mpair (f2p,E2p,E2ap)
    __shared__ float sS[128];

    const int tid = threadIdx.x, w = tid >> 5, l = tid & 31;
    const int bid  = blockIdx.x;
    const int tile = bid % 24;
    const int h    = (bid / 24) % NHEADS;
    const int g    = bid / (24 * NHEADS);
    const int gh   = g * NHEADS + h;
    const int nbase = tile * 128;

    const int r0 = w * 32 + (l >> 2);       // rows r0, r0+8, r0+16, r0+24

    // per-row-set fp16x2 broadcasts of (f1, E1, E1a)
    __half2 f1b[4], E1b[4], E1ab[4];
    #pragma unroll
    for (int j = 0; j < 4; j++) {
        float4 p1 = g_pf1[(size_t)gh * NN + nbase + r0 + 8*j];
        f1b[j]  = __float2half2_rn(p1.x);
        E1b[j]  = __float2half2_rn(p1.y);
        E1ab[j] = __float2half2_rn(p1.z);
    }
    const u32 bone = ((l >> 2) == 0) ? 0x3C003C00u : 0u;   // ones column at n=0

    const u32* abb  = g_abits + ((size_t)g * NN + nbase + r0) * (NN/32);  // row-set j: +j*8*96
    const u32* Whpg = g_whp + (size_t)gh * (NN/2) * NHID;
    const uint4* f2g = g_f2h + (size_t)gh * (NN/2);

    float c0[8][4], c1[8][4];
    #pragma unroll
    for (int t = 0; t < 8; t++) {
        c0[t][0]=0.f; c0[t][1]=0.f; c0[t][2]=0.f; c0[t][3]=0.f;
        c1[t][0]=0.f; c1[t][1]=0.f; c1[t][2]=0.f; c1[t][3]=0.f;
    }
    float cS0[4] = {0.f,0.f,0.f,0.f}, cS1[4] = {0.f,0.f,0.f,0.f};

    // staging geometry: thread covers mpair mp, o = og..og+15
    const int mp = tid >> 2;
    const int og = (tid & 3) * 16;

    uint4 wpre[4]; uint4 fpre = make_uint4(0,0,0,0);
    u32 abw[8];
    {
        const uint4* src = (const uint4*)(Whpg + (size_t)mp * NHID + og);
        #pragma unroll
        for (int j = 0; j < 4; j++) wpre[j] = src[j];
        if (tid < 32) fpre = f2g[tid];
        #pragma unroll
        for (int j = 0; j < 4; j++) {
            abw[2*j]     = abb[j * 8 * (NN/32)];
            abw[2*j + 1] = abb[j * 8 * (NN/32) + 1];
        }
    }

    for (int i = 0; i < NN/64; i++) {
        __syncthreads();
        {
            uint4* d = (uint4*)&WhP[mp * WP_STRIDE + og];
            #pragma unroll
            for (int j = 0; j < 4; j++) d[j] = wpre[j];
            if (tid < 32) f2HS[tid] = fpre;
        }
        u32 wl[8];
        #pragma unroll
        for (int j = 0; j < 8; j++) wl[j] = abw[j];
        __syncthreads();

        if (i + 1 < NN/64) {
            const uint4* src = (const uint4*)(Whpg + (size_t)((i+1)*32 + mp) * NHID + og);
            #pragma unroll
            for (int j = 0; j < 4; j++) wpre[j] = src[j];
            if (tid < 32) fpre = f2g[(i+1)*32 + tid];
            int wd = (i + 1) * 2;
            #pragma unroll
            for (int j = 0; j < 4; j++) {
                abw[2*j]     = abb[j * 8 * (NN/32) + wd];
                abw[2*j + 1] = abb[j * 8 * (NN/32) + wd + 1];
            }
        }

        #pragma unroll
        for (int kk = 0; kk < 4; kk++) {
            uint4 qa = f2HS[kk*8 + (l & 3)];        // mpairs m0,m0+1
            uint4 qb = f2HS[kk*8 + 4 + (l & 3)];    // mpairs m0+8,m0+9
            const int bb = (kk & 1) * 16 + 2 * (l & 3);
            u32 A0[4], A1[4];
            #pragma unroll
            for (int j = 0; j < 2; j++) {           // tile0: sets 0,1
                u32 wj = (kk < 2) ? wl[2*j] : wl[2*j + 1];
                A0[j]     = pgen(f1b[j], E1b[j], E1ab[j], qa.x, qa.y, qa.z, amask((wj >> bb) & 3u));
                A0[2 + j] = pgen(f1b[j], E1b[j], E1ab[j], qb.x, qb.y, qb.z, amask((wj >> (bb+8)) & 3u));
            }
            #pragma unroll
            for (int j = 0; j < 2; j++) {           // tile1: sets 2,3
                u32 wj = (kk < 2) ? wl[4 + 2*j] : wl[4 + 2*j + 1];
                A1[j]     = pgen(f1b[2+j], E1b[2+j], E1ab[2+j], qa.x, qa.y, qa.z, amask((wj >> bb) & 3u));
                A1[2 + j] = pgen(f1b[2+j], E1b[2+j], E1ab[2+j], qb.x, qb.y, qb.z, amask((wj >> (bb+8)) & 3u));
            }
            mma_f16(cS0, A0[0], A0[1], A0[2], A0[3], bone, bone);
            mma_f16(cS1, A1[0], A1[1], A1[2], A1[3], bone, bone);
            const u32* base0 = &WhP[(kk*8 + (l & 3)) * WP_STRIDE + (l >> 2)];
            #pragma unroll
            for (int t = 0; t < 8; t++) {
                u32 b0 = base0[8 * t];
                u32 b1 = base0[4 * WP_STRIDE + 8 * t];
                mma_f16(c0[t], A0[0], A0[1], A0[2], A0[3], b0, b1);
                mma_f16(c1[t], A1[0], A1[1], A1[2], A1[3], b0, b1);
            }
        }
    }

    // row sums from ones-column mma (column 0, lanes with (l&3)==0)
    if ((l & 3) == 0) {
        sS[r0]      = cS0[0];
        sS[r0 + 8]  = cS0[2];
        sS[r0 + 16] = cS1[0];
        sS[r0 + 24] = cS1[2];
    }
    __syncthreads();
    const float i0 = 1.0f / sS[r0];
    const float i1 = 1.0f / sS[r0 + 8];
    const float i2 = 1.0f / sS[r0 + 16];
    const float i3 = 1.0f / sS[r0 + 24];

    float* d0 = g_hcat + ((size_t)g * NN + nbase + r0     ) * (NHEADS*NHID) + h * NHID;
    float* d1 = g_hcat + ((size_t)g * NN + nbase + r0 + 8 ) * (NHEADS*NHID) + h * NHID;
    float* d2 = g_hcat + ((size_t)g * NN + nbase + r0 + 16) * (NHEADS*NHID) + h * NHID;
    float* d3 = g_hcat + ((size_t)g * NN + nbase + r0 + 24) * (NHEADS*NHID) + h * NHID;
    #pragma unroll
    for (int t = 0; t < 8; t++) {
        int col = 8 * t + 2 * (l & 3);
        float2 v;
        v.x = eluf(c0[t][0] * i0); v.y = eluf(c0[t][1] * i0);
        *(float2*)(d0 + col) = v;
        v.x = eluf(c0[t][2] * i1); v.y = eluf(c0[t][3] * i1);
        *(float2*)(d1 + col) = v;
        v.x = eluf(c1[t][0] * i2); v.y = eluf(c1[t][1] * i2);
        *(float2*)(d2 + col) = v;
        v.x = eluf(c1[t][2] * i3); v.y = eluf(c1[t][3] * i3);
        *(float2*)(d3 + col) = v;
    }
}

// ---------------------------------------------------------------------------
// K4: xi = elu(hcat . W_int + b)
// ---------------------------------------------------------------------------
__global__ void k_xi(const float* __restrict__ W_int, const float* __restrict__ b_int)
{
    __shared__ float Ws[NCLASS * 256];
    __shared__ float bs[NCLASS];
    const int tid = threadIdx.x, w = tid >> 5, lane = tid & 31;
    #pragma unroll
    for (int j = 0; j < 4; j++)
        *(float4*)&Ws[tid * 4 + j * 1024] = *(const float4*)(W_int + tid * 4 + j * 1024);
    if (tid < NCLASS) bs[tid] = b_int[tid];
    __syncthreads();

    long idx = (long)blockIdx.x * 8 + w;
    int g = (int)(idx / NN);
    int n = (int)(idx % NN);
    const float* hrow = g_hcat + ((size_t)g * NN + n) * 256;
    float v[8];
    #pragma unroll
    for (int j = 0; j < 8; j++) v[j] = hrow[lane + 32 * j];

    for (int c = 0; c < NCLASS; c++) {
        const float* wc = Ws + c * 256;
        float s = 0.f;
        #pragma unroll
        for (int j = 0; j < 8; j++) s += v[j] * wc[lane + 32 * j];
        #pragma unroll
        for (int o = 16; o >= 1; o >>= 1) s += __shfl_xor_sync(0xffffffffu, s, o);
        if (lane == 0) {
            float t = s + bs[c];
            t = (t > 0.f) ? t : expm1f(t);
            g_xib[(size_t)n * (NGRAPH*NCLASS) + g * NCLASS + c] = t;
        }
    }
}

// ---------------------------------------------------------------------------
// K5: out = log_softmax(xib @ W_fus^T + b_fus)
// ---------------------------------------------------------------------------
__global__ void k_out(const float* __restrict__ W_fus, const float* __restrict__ b_fus,
                      float* __restrict__ out)
{
    __shared__ float Wf[NCLASS * 48];
    __shared__ float bf[NCLASS];
    const int tid = threadIdx.x;
    for (int i = tid; i < NCLASS * 48; i += 256) Wf[i] = W_fus[i];
    if (tid < NCLASS) bf[tid] = b_fus[tid];
    __syncthreads();

    int n = blockIdx.x * 256 + tid;
    const float* xr = g_xib + (size_t)n * 48;
    float xv[48];
    #pragma unroll
    for (int j = 0; j < 48; j++) xv[j] = xr[j];

    float o[NCLASS];
    float mx = -FLT_MAX;
    #pragma unroll
    for (int c = 0; c < NCLASS; c++) {
        float s = bf[c];
        #pragma unroll
        for (int j = 0; j < 48; j++) s += xv[j] * Wf[c * 48 + j];
        o[c] = s;
        mx = fmaxf(mx, s);
    }
    float sum = 0.f;
    #pragma unroll
    for (int c = 0; c < NCLASS; c++) sum += expf(o[c] - mx);
    float lse = mx + logf(sum);
    float* dst = out + (size_t)n * NCLASS;
    #pragma unroll
    for (int c = 0; c < NCLASS; c++) dst[c] = o[c] - lse;
}

// ---------------------------------------------------------------------------
// K6: l1 = mean |W_fus|
// ---------------------------------------------------------------------------
__global__ void k_l1(const float* __restrict__ W_fus, float* __restrict__ out, int out_size)
{
    __shared__ float red[256];
    int tid = threadIdx.x;
    float s = 0.f;
    for (int i = tid; i < NCLASS * 48; i += 256) s += fabsf(W_fus[i]);
    red[tid] = s;
    __syncthreads();
    for (int o = 128; o >= 1; o >>= 1) {
        if (tid < o) red[tid] += red[tid + o];
        __syncthreads();
    }
    if (tid == 0) {
        float l1 = red[0] / (float)(NCLASS * 48);
        for (int i = NN * NCLASS; i < out_size; i++) out[i] = l1;
    }
}

extern "C" void kernel_launch(void* const* d_in, const int* in_sizes, int n_in,
                              void* d_out, int out_size)
{
    const float* x     = (const float*)d_in[0];
    const int*   adj   = (const int*)  d_in[1];
    const float* W     = (const float*)d_in[2];
    const float* a     = (const float*)d_in[3];
    const float* W_int = (const float*)d_in[4];
    const float* b_int = (const float*)d_in[5];
    const float* W_fus = (const float*)d_in[6];
    const float* b_fus = (const float*)d_in[7];
    float* out = (float*)d_out;

    k_cvt   <<<(XP_TOTAL + WP_TOTAL + 511) / 512, 512>>>(x, W);
    k_pack  <<<NGRAPH * NN / 8, 256>>>(adj);
    k_wh_mma<<<dim3(NN/128, GH), 256>>>(a);
    k_att_mma<<<NGRAPH * NHEADS * (NN/128), 128>>>();
    k_xi    <<<NGRAPH * NN / 8, 256>>>(W_int, b_int);
    k_out   <<<NN/256, 256>>>(W_fus, b_fus, out);
    k_l1    <<<1, 256>>>(W_fus, out, out_size);
}